// round 1
// baseline (speedup 1.0000x reference)
#include <cuda_runtime.h>
#include <math.h>

// ---------------- problem constants ----------------
#define Ncfg 16
#define Ccfg 16
#define Tcfg 300
#define Vcfg 25
#define Dcfg 400           // C*V
#define DH   200           // head dim (H=2)
#define FFc  1600
#define Lw   9
#define Wcfg 291           // T - L
#define NW   (Ncfg*Wcfg)   // 4656 windows
#define M2   (NW*Lw)       // 41904 window rows
#define NT   (Ncfg*Tcfg)   // 4800 tokens

// ---------------- scratch (device globals; no allocs allowed) ----------------
__device__ float g_xs  [NT * Dcfg];            // tokens after permute + PE   (7.7 MB)
__device__ float g_qkv [NT * 3 * Dcfg];        // per-token QKV               (23 MB)
__device__ float g_attn[M2 * Dcfg];            // attention output            (67 MB)
__device__ float g_h1  [M2 * Dcfg];            // post-LN1                    (67 MB)
__device__ float g_ff  [(size_t)M2 * FFc];     // FFN intermediate            (268 MB)
__device__ float g_h2  [M2 * Dcfg];            // post-LN2                    (67 MB)

// ---------------- kernel 1: [N,C,T,V] -> [N,T,D] + positional encoding ----------------
__global__ void k_build_xs(const float* __restrict__ x, const float* __restrict__ pe) {
    int idx = blockIdx.x * 256 + threadIdx.x;
    if (idx >= NT * Dcfg) return;
    int d   = idx % Dcfg;
    int row = idx / Dcfg;
    int t = row % Tcfg, n = row / Tcfg;
    int v = d / Ccfg,   c = d % Ccfg;
    g_xs[idx] = x[((size_t)(n * Ccfg + c) * Tcfg + t) * Vcfg + v] + pe[t * Dcfg + d];
}

// ---------------- SGEMM: C[M,Nn] = A[M,K] @ B[Nn,K]^T + bias, fused epilogues ----------
// EPI: 0 = bias only, 1 = bias+gelu(exact), 2 = bias + residual gathered from g_xs
//      (window-row -> token-row map), 3 = bias + residual same-row (res stride Nn)
template <int EPI>
__global__ void __launch_bounds__(256) k_sgemm(
    const float* __restrict__ A, const float* __restrict__ B,
    const float* __restrict__ bias, const float* __restrict__ res,
    float* __restrict__ C, int M, int Nn, int K)
{
    __shared__ float As[8][128];
    __shared__ float Bs[8][128];
    int tid = threadIdx.x;
    int lr = tid >> 1;               // 0..127 : tile row
    int lk = (tid & 1) * 4;          // 0 or 4 : k offset (float4)
    int aRow = blockIdx.y * 128 + lr;
    int bRow = blockIdx.x * 128 + lr;
    int tx = tid & 15, ty = tid >> 4;

    float acc[8][8];
#pragma unroll
    for (int j = 0; j < 8; j++)
#pragma unroll
        for (int i = 0; i < 8; i++) acc[j][i] = 0.f;

    const float4 z4 = make_float4(0.f, 0.f, 0.f, 0.f);
    for (int k0 = 0; k0 < K; k0 += 8) {
        float4 av = (aRow < M)  ? *(const float4*)(A + (size_t)aRow * K + k0 + lk) : z4;
        float4 bv = (bRow < Nn) ? *(const float4*)(B + (size_t)bRow * K + k0 + lk) : z4;
        As[lk + 0][lr] = av.x; As[lk + 1][lr] = av.y; As[lk + 2][lr] = av.z; As[lk + 3][lr] = av.w;
        Bs[lk + 0][lr] = bv.x; Bs[lk + 1][lr] = bv.y; Bs[lk + 2][lr] = bv.z; Bs[lk + 3][lr] = bv.w;
        __syncthreads();
#pragma unroll
        for (int kk = 0; kk < 8; kk++) {
            float4 a0 = *(const float4*)&As[kk][ty * 4];
            float4 a1 = *(const float4*)&As[kk][64 + ty * 4];
            float4 b0 = *(const float4*)&Bs[kk][tx * 4];
            float4 b1 = *(const float4*)&Bs[kk][64 + tx * 4];
            float a[8] = {a0.x, a0.y, a0.z, a0.w, a1.x, a1.y, a1.z, a1.w};
            float b[8] = {b0.x, b0.y, b0.z, b0.w, b1.x, b1.y, b1.z, b1.w};
#pragma unroll
            for (int j = 0; j < 8; j++)
#pragma unroll
                for (int i = 0; i < 8; i++) acc[j][i] = fmaf(a[j], b[i], acc[j][i]);
        }
        __syncthreads();
    }

#pragma unroll
    for (int jh = 0; jh < 2; jh++)
#pragma unroll
    for (int j = 0; j < 4; j++) {
        int row = blockIdx.y * 128 + jh * 64 + ty * 4 + j;
        if (row >= M) continue;
        int trow = 0;
        if (EPI == 2) {
            int n = row / (Wcfg * Lw);
            int rem = row - n * (Wcfg * Lw);
            int w = rem / Lw, l = rem - w * Lw;
            trow = (n * Tcfg + w + l) * Dcfg;
        }
#pragma unroll
        for (int ih = 0; ih < 2; ih++) {
            int col = blockIdx.x * 128 + ih * 64 + tx * 4;
            if (col >= Nn) continue;
            float4 bb = *(const float4*)(bias + col);
            float bv[4] = {bb.x, bb.y, bb.z, bb.w};
            float vals[4];
#pragma unroll
            for (int i = 0; i < 4; i++) {
                float vv = acc[jh * 4 + j][ih * 4 + i] + bv[i];
                if (EPI == 1) vv = 0.5f * vv * (1.f + erff(vv * 0.70710678118654752440f));
                if (EPI == 2) vv += res[trow + col + i];
                if (EPI == 3) vv += res[(size_t)row * Nn + col + i];
                vals[i] = vv;
            }
            *(float4*)(C + (size_t)row * Nn + col) =
                make_float4(vals[0], vals[1], vals[2], vals[3]);
        }
    }
}

// ---------------- attention: one block per window (L=9, H=2, dh=200) ----------------
__global__ void __launch_bounds__(256) k_attn() {
    __shared__ float sbuf[Lw * 3 * Dcfg];     // 9 x 1200 = 43.2 KB
    __shared__ float ssc[2 * Lw * Lw];        // 162 scores
    int b = blockIdx.x;                       // window id
    int n = b / Wcfg, w = b - n * Wcfg;
    int tid = threadIdx.x;

    for (int idx = tid; idx < Lw * 3 * Dcfg; idx += 256) {
        int t = idx / (3 * Dcfg), col = idx - t * (3 * Dcfg);
        sbuf[idx] = g_qkv[(size_t)(n * Tcfg + w + t) * (3 * Dcfg) + col];
    }
    __syncthreads();

    int wid = tid >> 5, lane = tid & 31;
    for (int p = wid; p < 162; p += 8) {
        int h = p / 81, rem = p - h * 81;
        int i = rem / 9, j = rem - i * 9;
        const float* qp = &sbuf[i * 1200 + h * DH];
        const float* kp = &sbuf[j * 1200 + Dcfg + h * DH];
        float s = 0.f;
        for (int d = lane; d < DH; d += 32) s += qp[d] * kp[d];
#pragma unroll
        for (int o = 16; o; o >>= 1) s += __shfl_xor_sync(0xffffffffu, s, o);
        if (lane == 0) ssc[p] = s * 0.07071067811865475f;   // 1/sqrt(200)
    }
    __syncthreads();

    if (tid < 18) {                        // softmax row (h,i)
        float* r = &ssc[tid * 9];
        float m = r[0];
#pragma unroll
        for (int j = 1; j < 9; j++) m = fmaxf(m, r[j]);
        float s = 0.f;
#pragma unroll
        for (int j = 0; j < 9; j++) { float e = expf(r[j] - m); r[j] = e; s += e; }
        float inv = 1.f / s;
#pragma unroll
        for (int j = 0; j < 9; j++) r[j] *= inv;
    }
    __syncthreads();

    size_t obase = (size_t)b * Lw * Dcfg;
    for (int idx = tid; idx < Lw * Dcfg; idx += 256) {
        int i = idx / Dcfg, c = idx - i * Dcfg;
        int h = c / DH;
        const float* att = &ssc[(h * 9 + i) * 9];
        float s = 0.f;
#pragma unroll
        for (int j = 0; j < 9; j++) s += att[j] * sbuf[j * 1200 + 2 * Dcfg + c];
        g_attn[obase + idx] = s;
    }
}

// ---------------- layernorm over rows of 400, in place ----------------
__global__ void __launch_bounds__(128) k_ln(float* __restrict__ X,
                                            const float* __restrict__ g,
                                            const float* __restrict__ bb) {
    int row = blockIdx.x;
    float* xr = X + (size_t)row * Dcfg;
    int tid = threadIdx.x;
    float s = 0.f, s2 = 0.f;
    for (int i = tid; i < Dcfg; i += 128) { float v = xr[i]; s += v; s2 += v * v; }
#pragma unroll
    for (int o = 16; o; o >>= 1) {
        s  += __shfl_xor_sync(0xffffffffu, s, o);
        s2 += __shfl_xor_sync(0xffffffffu, s2, o);
    }
    __shared__ float sh[10];
    int wid = tid >> 5, lane = tid & 31;
    if (lane == 0) { sh[wid] = s; sh[4 + wid] = s2; }
    __syncthreads();
    if (tid == 0) {
        float ts  = sh[0] + sh[1] + sh[2] + sh[3];
        float ts2 = sh[4] + sh[5] + sh[6] + sh[7];
        float mu  = ts * (1.f / Dcfg);
        float var = ts2 * (1.f / Dcfg) - mu * mu;
        sh[8] = mu; sh[9] = rsqrtf(var + 1e-5f);
    }
    __syncthreads();
    float mu = sh[8], rstd = sh[9];
    for (int i = tid; i < Dcfg; i += 128)
        xr[i] = (xr[i] - mu) * rstd * g[i] + bb[i];
}

// ---------------- overlap-add as gather + output permute [N,T,D]->[N,C,T,V] --------
__global__ void k_gather(float* __restrict__ out) {
    int idx = blockIdx.x * 256 + threadIdx.x;
    if (idx >= NT * Dcfg) return;
    int d = idx % Dcfg;
    int r = idx / Dcfg;
    int t = r % Tcfg, n = r / Tcfg;
    float acc = 0.f;
    int lmax = t < 8 ? t : 8;
    for (int l = 0; l <= lmax; l++) {
        int w0 = 2 * (t - l);
        if (w0 < Wcfg) {
            acc += g_h2[((size_t)((n * Wcfg + w0) * Lw + l)) * Dcfg + d];
            if (w0 + 1 < Wcfg)
                acc += g_h2[((size_t)((n * Wcfg + w0 + 1) * Lw + l)) * Dcfg + d];
        }
    }
    int v = d / Ccfg, c = d % Ccfg;
    out[((size_t)(n * Ccfg + c) * Tcfg + t) * Vcfg + v] = acc;
}

// ---------------- launch ----------------
extern "C" void kernel_launch(void* const* d_in, const int* in_sizes, int n_in,
                              void* d_out, int out_size) {
    (void)in_sizes; (void)n_in; (void)out_size;
    const float* x     = (const float*)d_in[0];
    const float* pe    = (const float*)d_in[1];
    const float* w_in  = (const float*)d_in[2];
    const float* b_in  = (const float*)d_in[3];
    const float* w_out = (const float*)d_in[4];
    const float* b_out = (const float*)d_in[5];
    const float* w1    = (const float*)d_in[6];
    const float* b1    = (const float*)d_in[7];
    const float* w2    = (const float*)d_in[8];
    const float* b2    = (const float*)d_in[9];
    const float* ln1g  = (const float*)d_in[10];
    const float* ln1b  = (const float*)d_in[11];
    const float* ln2g  = (const float*)d_in[12];
    const float* ln2b  = (const float*)d_in[13];
    float* out = (float*)d_out;

    float *xs, *qkv, *attn, *h1, *ff, *h2;
    cudaGetSymbolAddress((void**)&xs,   g_xs);
    cudaGetSymbolAddress((void**)&qkv,  g_qkv);
    cudaGetSymbolAddress((void**)&attn, g_attn);
    cudaGetSymbolAddress((void**)&h1,   g_h1);
    cudaGetSymbolAddress((void**)&ff,   g_ff);
    cudaGetSymbolAddress((void**)&h2,   g_h2);

    // 1. permute + PE
    k_build_xs<<<(NT * Dcfg + 255) / 256, 256>>>(x, pe);

    // 2. per-token QKV:  [4800,400] x [1200,400]^T
    {
        dim3 g((3 * Dcfg + 127) / 128, (NT + 127) / 128);
        k_sgemm<0><<<g, 256>>>(xs, w_in, b_in, nullptr, qkv, NT, 3 * Dcfg, Dcfg);
    }

    // 3. windowed attention
    k_attn<<<NW, 256>>>();

    // 4. out-proj + residual (gathered token) -> LN1
    {
        dim3 g((Dcfg + 127) / 128, (M2 + 127) / 128);
        k_sgemm<2><<<g, 256>>>(attn, w_out, b_out, xs, h1, M2, Dcfg, Dcfg);
    }
    k_ln<<<M2, 128>>>(h1, ln1g, ln1b);

    // 5. FFN up + exact gelu
    {
        dim3 g((FFc + 127) / 128, (M2 + 127) / 128);
        k_sgemm<1><<<g, 256>>>(h1, w1, b1, nullptr, ff, M2, FFc, Dcfg);
    }
    // 6. FFN down + residual -> LN2
    {
        dim3 g((Dcfg + 127) / 128, (M2 + 127) / 128);
        k_sgemm<3><<<g, 256>>>(ff, w2, b2, h1, h2, M2, Dcfg, FFc);
    }
    k_ln<<<M2, 128>>>(h2, ln2g, ln2b);

    // 7. overlap-add gather + output permute
    k_gather<<<(NT * Dcfg + 255) / 256, 256>>>(out);
}

// round 4
// speedup vs baseline: 1.2768x; 1.2768x over previous
#include <cuda_runtime.h>
#include <math.h>

// ---------------- problem constants ----------------
#define Ncfg 16
#define Ccfg 16
#define Tcfg 300
#define Vcfg 25
#define Dcfg 400           // C*V
#define DH   200           // head dim (H=2)
#define FFc  1600
#define Lw   9
#define Wcfg 291           // T - L
#define NW   (Ncfg*Wcfg)   // 4656 windows
#define M2   (NW*Lw)       // 41904 window rows
#define NT   (Ncfg*Tcfg)   // 4800 tokens

// ---------------- scratch (device globals; no allocs allowed) ----------------
__device__ float g_xs  [NT * Dcfg];
__device__ float g_qkv [NT * 3 * Dcfg];
__device__ float g_attn[M2 * Dcfg];
__device__ float g_h1  [M2 * Dcfg];
__device__ float g_ff  [(size_t)M2 * FFc];
__device__ float g_h2  [M2 * Dcfg];

// ---------------- f32x2 helpers ----------------
__device__ __forceinline__ unsigned long long pack2(float x, float y) {
    unsigned long long r;
    asm("mov.b64 %0, {%1, %2};" : "=l"(r) : "f"(x), "f"(y));
    return r;
}
__device__ __forceinline__ void fma2(unsigned long long& d,
                                     unsigned long long a,
                                     unsigned long long b) {
    asm("fma.rn.f32x2 %0, %1, %2, %0;" : "+l"(d) : "l"(a), "l"(b));
}
__device__ __forceinline__ float2 unpack2(unsigned long long v) {
    float2 r;
    asm("mov.b64 {%0, %1}, %2;" : "=f"(r.x), "=f"(r.y) : "l"(v));
    return r;
}

// ---------------- kernel 1: [N,C,T,V] -> [N,T,D] + positional encoding -------------
__global__ void k_build_xs(const float* __restrict__ x, const float* __restrict__ pe) {
    int idx = blockIdx.x * 256 + threadIdx.x;
    if (idx >= NT * Dcfg) return;
    int d   = idx % Dcfg;
    int row = idx / Dcfg;
    int t = row % Tcfg, n = row / Tcfg;
    int v = d / Ccfg,   c = d % Ccfg;
    g_xs[idx] = x[((size_t)(n * Ccfg + c) * Tcfg + t) * Vcfg + v] + pe[t * Dcfg + d];
}

// ---------------- SGEMM: C[M,Nn] = A[M,K] @ B[Nn,K]^T + bias, fused epilogues ------
// EPI: 0 = bias only, 1 = bias+gelu(exact), 2 = bias + residual gathered from g_xs,
//      3 = bias + residual same-row (stride Nn)
// Inner loop on packed fma.rn.f32x2 (FFMA2), double-buffered smem.
template <int EPI>
__global__ void __launch_bounds__(256, 2) k_sgemm(
    const float* __restrict__ A, const float* __restrict__ B,
    const float* __restrict__ bias, const float* __restrict__ res,
    float* __restrict__ C, int M, int Nn, int K)
{
    __shared__ float As[2][8][128];
    __shared__ float Bs[2][8][128];
    int tid = threadIdx.x;
    int lr = tid >> 1;               // 0..127 : tile row
    int lk = (tid & 1) * 4;          // 0 or 4 : k offset (float4)
    int aRow = blockIdx.y * 128 + lr;
    int bRow = blockIdx.x * 128 + lr;
    int tx = tid & 15, ty = tid >> 4;

    // 8x8 accumulators as 8x4 packed f32x2 pairs
    unsigned long long acc[8][4];
#pragma unroll
    for (int j = 0; j < 8; j++)
#pragma unroll
        for (int i = 0; i < 4; i++) acc[j][i] = 0ull;

    const float4 z4 = make_float4(0.f, 0.f, 0.f, 0.f);
    const bool aOk = (aRow < M), bOk = (bRow < Nn);
    const float* Ap = A + (size_t)aRow * K + lk;
    const float* Bp = B + (size_t)bRow * K + lk;

    // prologue: tile 0 -> buffer 0
    {
        float4 av = aOk ? *(const float4*)(Ap) : z4;
        float4 bv = bOk ? *(const float4*)(Bp) : z4;
        As[0][lk + 0][lr] = av.x; As[0][lk + 1][lr] = av.y;
        As[0][lk + 2][lr] = av.z; As[0][lk + 3][lr] = av.w;
        Bs[0][lk + 0][lr] = bv.x; Bs[0][lk + 1][lr] = bv.y;
        Bs[0][lk + 2][lr] = bv.z; Bs[0][lk + 3][lr] = bv.w;
    }
    __syncthreads();

    int buf = 0;
    for (int k0 = 8; k0 < K; k0 += 8) {
        // issue next global loads early (latency overlapped with compute)
        float4 av = aOk ? *(const float4*)(Ap + k0) : z4;
        float4 bv = bOk ? *(const float4*)(Bp + k0) : z4;

#pragma unroll
        for (int kk = 0; kk < 8; kk++) {
            float4 a0 = *(const float4*)&As[buf][kk][ty * 4];
            float4 a1 = *(const float4*)&As[buf][kk][64 + ty * 4];
            ulonglong2 q0 = *(const ulonglong2*)&Bs[buf][kk][tx * 4];
            ulonglong2 q1 = *(const ulonglong2*)&Bs[buf][kk][64 + tx * 4];
            unsigned long long bu[4] = {q0.x, q0.y, q1.x, q1.y};
            float a[8] = {a0.x, a0.y, a0.z, a0.w, a1.x, a1.y, a1.z, a1.w};
#pragma unroll
            for (int j = 0; j < 8; j++) {
                unsigned long long ap = pack2(a[j], a[j]);
#pragma unroll
                for (int i = 0; i < 4; i++) fma2(acc[j][i], ap, bu[i]);
            }
        }
        int nb = buf ^ 1;
        As[nb][lk + 0][lr] = av.x; As[nb][lk + 1][lr] = av.y;
        As[nb][lk + 2][lr] = av.z; As[nb][lk + 3][lr] = av.w;
        Bs[nb][lk + 0][lr] = bv.x; Bs[nb][lk + 1][lr] = bv.y;
        Bs[nb][lk + 2][lr] = bv.z; Bs[nb][lk + 3][lr] = bv.w;
        __syncthreads();
        buf = nb;
    }
    // last tile
#pragma unroll
    for (int kk = 0; kk < 8; kk++) {
        float4 a0 = *(const float4*)&As[buf][kk][ty * 4];
        float4 a1 = *(const float4*)&As[buf][kk][64 + ty * 4];
        ulonglong2 q0 = *(const ulonglong2*)&Bs[buf][kk][tx * 4];
        ulonglong2 q1 = *(const ulonglong2*)&Bs[buf][kk][64 + tx * 4];
        unsigned long long bu[4] = {q0.x, q0.y, q1.x, q1.y};
        float a[8] = {a0.x, a0.y, a0.z, a0.w, a1.x, a1.y, a1.z, a1.w};
#pragma unroll
        for (int j = 0; j < 8; j++) {
            unsigned long long ap = pack2(a[j], a[j]);
#pragma unroll
            for (int i = 0; i < 4; i++) fma2(acc[j][i], ap, bu[i]);
        }
    }

    // epilogue
#pragma unroll
    for (int jh = 0; jh < 2; jh++)
#pragma unroll
    for (int j = 0; j < 4; j++) {
        int row = blockIdx.y * 128 + jh * 64 + ty * 4 + j;
        if (row >= M) continue;
        int trow = 0;
        if (EPI == 2) {
            int n = row / (Wcfg * Lw);
            int rem = row - n * (Wcfg * Lw);
            int w = rem / Lw, l = rem - w * Lw;
            trow = (n * Tcfg + w + l) * Dcfg;
        }
#pragma unroll
        for (int ih = 0; ih < 2; ih++) {
            int col = blockIdx.x * 128 + ih * 64 + tx * 4;
            if (col >= Nn) continue;
            float4 bb = *(const float4*)(bias + col);
            float bv[4] = {bb.x, bb.y, bb.z, bb.w};
            float2 p0 = unpack2(acc[jh * 4 + j][ih * 2 + 0]);
            float2 p1 = unpack2(acc[jh * 4 + j][ih * 2 + 1]);
            float av[4] = {p0.x, p0.y, p1.x, p1.y};
            float vals[4];
#pragma unroll
            for (int i = 0; i < 4; i++) {
                float vv = av[i] + bv[i];
                if (EPI == 1) vv = 0.5f * vv * (1.f + erff(vv * 0.70710678118654752440f));
                if (EPI == 2) vv += res[trow + col + i];
                if (EPI == 3) vv += res[(size_t)row * Nn + col + i];
                vals[i] = vv;
            }
            *(float4*)(C + (size_t)row * Nn + col) =
                make_float4(vals[0], vals[1], vals[2], vals[3]);
        }
    }
}

// ---------------- attention: one block per window (L=9, H=2, dh=200) ---------------
__global__ void __launch_bounds__(256) k_attn() {
    __shared__ float sbuf[Lw * 3 * Dcfg];     // 9 x 1200 = 43.2 KB
    __shared__ float ssc[2 * Lw * Lw];
    int b = blockIdx.x;
    int n = b / Wcfg, w = b - n * Wcfg;
    int tid = threadIdx.x;

    for (int idx = tid; idx < Lw * 3 * Dcfg; idx += 256) {
        int t = idx / (3 * Dcfg), col = idx - t * (3 * Dcfg);
        sbuf[idx] = g_qkv[(size_t)(n * Tcfg + w + t) * (3 * Dcfg) + col];
    }
    __syncthreads();

    int wid = tid >> 5, lane = tid & 31;
    for (int p = wid; p < 162; p += 8) {
        int h = p / 81, rem = p - h * 81;
        int i = rem / 9, j = rem - i * 9;
        const float* qp = &sbuf[i * 1200 + h * DH];
        const float* kp = &sbuf[j * 1200 + Dcfg + h * DH];
        float s = 0.f;
        for (int d = lane; d < DH; d += 32) s += qp[d] * kp[d];
#pragma unroll
        for (int o = 16; o; o >>= 1) s += __shfl_xor_sync(0xffffffffu, s, o);
        if (lane == 0) ssc[p] = s * 0.07071067811865475f;   // 1/sqrt(200)
    }
    __syncthreads();

    if (tid < 18) {
        float* r = &ssc[tid * 9];
        float m = r[0];
#pragma unroll
        for (int j = 1; j < 9; j++) m = fmaxf(m, r[j]);
        float s = 0.f;
#pragma unroll
        for (int j = 0; j < 9; j++) { float e = expf(r[j] - m); r[j] = e; s += e; }
        float inv = 1.f / s;
#pragma unroll
        for (int j = 0; j < 9; j++) r[j] *= inv;
    }
    __syncthreads();

    size_t obase = (size_t)b * Lw * Dcfg;
    for (int idx = tid; idx < Lw * Dcfg; idx += 256) {
        int i = idx / Dcfg, c = idx - i * Dcfg;
        int h = c / DH;
        const float* att = &ssc[(h * 9 + i) * 9];
        float s = 0.f;
#pragma unroll
        for (int j = 0; j < 9; j++) s += att[j] * sbuf[j * 1200 + 2 * Dcfg + c];
        g_attn[obase + idx] = s;
    }
}

// ---------------- layernorm over rows of 400, in place ----------------
__global__ void __launch_bounds__(128) k_ln(float* __restrict__ X,
                                            const float* __restrict__ g,
                                            const float* __restrict__ bb) {
    int row = blockIdx.x;
    float* xr = X + (size_t)row * Dcfg;
    int tid = threadIdx.x;
    float s = 0.f, s2 = 0.f;
    for (int i = tid; i < Dcfg; i += 128) { float v = xr[i]; s += v; s2 += v * v; }
#pragma unroll
    for (int o = 16; o; o >>= 1) {
        s  += __shfl_xor_sync(0xffffffffu, s, o);
        s2 += __shfl_xor_sync(0xffffffffu, s2, o);
    }
    __shared__ float sh[10];
    int wid = tid >> 5, lane = tid & 31;
    if (lane == 0) { sh[wid] = s; sh[4 + wid] = s2; }
    __syncthreads();
    if (tid == 0) {
        float ts  = sh[0] + sh[1] + sh[2] + sh[3];
        float ts2 = sh[4] + sh[5] + sh[6] + sh[7];
        float mu  = ts * (1.f / Dcfg);
        float var = ts2 * (1.f / Dcfg) - mu * mu;
        sh[8] = mu; sh[9] = rsqrtf(var + 1e-5f);
    }
    __syncthreads();
    float mu = sh[8], rstd = sh[9];
    for (int i = tid; i < Dcfg; i += 128)
        xr[i] = (xr[i] - mu) * rstd * g[i] + bb[i];
}

// ---------------- overlap-add as gather + output permute [N,T,D]->[N,C,T,V] --------
__global__ void k_gather(float* __restrict__ out) {
    int idx = blockIdx.x * 256 + threadIdx.x;
    if (idx >= NT * Dcfg) return;
    int d = idx % Dcfg;
    int r = idx / Dcfg;
    int t = r % Tcfg, n = r / Tcfg;
    float acc = 0.f;
    int lmax = t < 8 ? t : 8;
    for (int l = 0; l <= lmax; l++) {
        int w0 = 2 * (t - l);
        if (w0 < Wcfg) {
            acc += g_h2[((size_t)((n * Wcfg + w0) * Lw + l)) * Dcfg + d];
            if (w0 + 1 < Wcfg)
                acc += g_h2[((size_t)((n * Wcfg + w0 + 1) * Lw + l)) * Dcfg + d];
        }
    }
    int v = d / Ccfg, c = d % Ccfg;
    out[((size_t)(n * Ccfg + c) * Tcfg + t) * Vcfg + v] = acc;
}

// ---------------- launch ----------------
extern "C" void kernel_launch(void* const* d_in, const int* in_sizes, int n_in,
                              void* d_out, int out_size) {
    (void)in_sizes; (void)n_in; (void)out_size;
    const float* x     = (const float*)d_in[0];
    const float* pe    = (const float*)d_in[1];
    const float* w_in  = (const float*)d_in[2];
    const float* b_in  = (const float*)d_in[3];
    const float* w_out = (const float*)d_in[4];
    const float* b_out = (const float*)d_in[5];
    const float* w1    = (const float*)d_in[6];
    const float* b1    = (const float*)d_in[7];
    const float* w2    = (const float*)d_in[8];
    const float* b2    = (const float*)d_in[9];
    const float* ln1g  = (const float*)d_in[10];
    const float* ln1b  = (const float*)d_in[11];
    const float* ln2g  = (const float*)d_in[12];
    const float* ln2b  = (const float*)d_in[13];
    float* out = (float*)d_out;

    float *xs, *qkv, *attn, *h1, *ff, *h2;
    cudaGetSymbolAddress((void**)&xs,   g_xs);
    cudaGetSymbolAddress((void**)&qkv,  g_qkv);
    cudaGetSymbolAddress((void**)&attn, g_attn);
    cudaGetSymbolAddress((void**)&h1,   g_h1);
    cudaGetSymbolAddress((void**)&ff,   g_ff);
    cudaGetSymbolAddress((void**)&h2,   g_h2);

    // 1. permute + PE
    k_build_xs<<<(NT * Dcfg + 255) / 256, 256>>>(x, pe);

    // 2. per-token QKV:  [4800,400] x [1200,400]^T
    {
        dim3 g((3 * Dcfg + 127) / 128, (NT + 127) / 128);
        k_sgemm<0><<<g, 256>>>(xs, w_in, b_in, nullptr, qkv, NT, 3 * Dcfg, Dcfg);
    }

    // 3. windowed attention
    k_attn<<<NW, 256>>>();

    // 4. out-proj + residual (gathered token) -> LN1
    {
        dim3 g((Dcfg + 127) / 128, (M2 + 127) / 128);
        k_sgemm<2><<<g, 256>>>(attn, w_out, b_out, xs, h1, M2, Dcfg, Dcfg);
    }
    k_ln<<<M2, 128>>>(h1, ln1g, ln1b);

    // 5. FFN up + exact gelu
    {
        dim3 g((FFc + 127) / 128, (M2 + 127) / 128);
        k_sgemm<1><<<g, 256>>>(h1, w1, b1, nullptr, ff, M2, FFc, Dcfg);
    }
    // 6. FFN down + residual -> LN2
    {
        dim3 g((Dcfg + 127) / 128, (M2 + 127) / 128);
        k_sgemm<3><<<g, 256>>>(ff, w2, b2, h1, h2, M2, Dcfg, FFc);
    }
    k_ln<<<M2, 128>>>(h2, ln2g, ln2b);

    // 7. overlap-add gather + output permute
    k_gather<<<(NT * Dcfg + 255) / 256, 256>>>(out);
}

// round 8
// speedup vs baseline: 1.5635x; 1.2246x over previous
#include <cuda_runtime.h>
#include <cuda_bf16.h>
#include <cstdint>
#include <math.h>

// ---------------- problem constants ----------------
#define Ncfg 16
#define Ccfg 16
#define Tcfg 300
#define Vcfg 25
#define Dcfg 400           // C*V
#define DH   200           // head dim (H=2)
#define FFc  1600
#define Lw   9
#define Wcfg 291           // T - L
#define NW   (Ncfg*Wcfg)   // 4656 windows
#define M2   (NW*Lw)       // 41904 window rows
#define NT   (Ncfg*Tcfg)   // 4800 tokens

typedef __nv_bfloat16 bf16;

// ---------------- scratch (device globals; no allocs allowed) ----------------
__device__ float g_xs   [NT * Dcfg];
__device__ bf16  g_xs_h [NT * Dcfg];
__device__ bf16  g_xs_l [NT * Dcfg];
__device__ bf16  g_win_h[3 * Dcfg * Dcfg];
__device__ bf16  g_win_l[3 * Dcfg * Dcfg];
__device__ bf16  g_wout_h[Dcfg * Dcfg];
__device__ bf16  g_wout_l[Dcfg * Dcfg];
__device__ bf16  g_w1_h [FFc * Dcfg];
__device__ bf16  g_w1_l [FFc * Dcfg];
__device__ bf16  g_w2_h [Dcfg * FFc];
__device__ bf16  g_w2_l [Dcfg * FFc];
__device__ float g_qkv  [NT * 3 * Dcfg];
__device__ bf16  g_attn_h[M2 * Dcfg];
__device__ bf16  g_attn_l[M2 * Dcfg];
__device__ float g_h1   [M2 * Dcfg];
__device__ bf16  g_h1_h [M2 * Dcfg];
__device__ bf16  g_h1_l [M2 * Dcfg];
__device__ bf16  g_ff_h [(size_t)M2 * FFc];
__device__ bf16  g_ff_l [(size_t)M2 * FFc];
__device__ float g_h2   [M2 * Dcfg];

// ---------------- helpers ----------------
__device__ __forceinline__ uint32_t smem_u32(const void* p) {
    uint32_t a;
    asm("{ .reg .u64 t; cvta.to.shared.u64 t, %1; cvt.u32.u64 %0, t; }" : "=r"(a) : "l"(p));
    return a;
}
#define SWZ128(o) ((o) ^ (((o) >> 3) & 0x70))

__device__ __forceinline__ void ldsm4(uint32_t* r, uint32_t a) {
    asm volatile("ldmatrix.sync.aligned.m8n8.x4.shared.b16 {%0,%1,%2,%3}, [%4];"
        : "=r"(r[0]), "=r"(r[1]), "=r"(r[2]), "=r"(r[3]) : "r"(a));
}
__device__ __forceinline__ void ldsm2(uint32_t* r, uint32_t a) {
    asm volatile("ldmatrix.sync.aligned.m8n8.x2.shared.b16 {%0,%1}, [%2];"
        : "=r"(r[0]), "=r"(r[1]) : "r"(a));
}
// mma m16n8k16 row.col f32 += bf16*bf16
__device__ __forceinline__ void mma16816(float* c, const uint32_t* a, const uint32_t* b) {
    asm volatile("mma.sync.aligned.m16n8k16.row.col.f32.bf16.bf16.f32 "
        "{%0,%1,%2,%3}, {%4,%5,%6,%7}, {%8,%9}, {%0,%1,%2,%3};"
        : "+f"(c[0]), "+f"(c[1]), "+f"(c[2]), "+f"(c[3])
        : "r"(a[0]), "r"(a[1]), "r"(a[2]), "r"(a[3]), "r"(b[0]), "r"(b[1]));
}

__device__ __forceinline__ void split32(float v, bf16& h, bf16& l) {
    h = __float2bfloat16(v);
    l = __float2bfloat16(v - __bfloat162float(h));
}

// ---------------- smem layout: 4 planes (Ah, Al, Bh, Bl) x double buffer -----------
#define TILE_BYTES 16384                 // 128 rows x 128B (64 bf16)
#define BUF_BYTES  (4 * TILE_BYTES)
#define SMEM_TOTAL (2 * BUF_BYTES)       // 131072

// load one 128x64 bf16 plane into swizzled smem (256 threads)
__device__ __forceinline__ void load_plane(const bf16* __restrict__ G, int rowBase,
                                           int rows, int K, int kbase, char* sdst) {
    int t = threadIdx.x;
    int r = t >> 1, half = t & 1;
    int gr = rowBase + r;
    bool rok = gr < rows;
    const bf16* gp = G + (size_t)gr * K;
#pragma unroll
    for (int i = 0; i < 4; i++) {
        int kc = kbase + half * 32 + i * 8;
        uint4 v = make_uint4(0u, 0u, 0u, 0u);
        if (rok && kc < K) v = *(const uint4*)(gp + kc);
        int boff = r * 128 + half * 64 + i * 16;
        *(uint4*)(sdst + SWZ128(boff)) = v;
    }
}

// ---------------- HMMA GEMM: C[M,Nn] = A[M,K] @ B[Nn,K]^T + bias, epilogues --------
// A,B as split bf16 planes.  acc += Ah*Bh + Ah*Bl + Al*Bh  (fp32 accumulate)
// EPI: 0 bias->fp32 | 1 bias+gelu->bf16 hi/lo planes | 2 bias+res(gathered xs)->fp32
//      3 bias+res(row)->fp32
template <int EPI>
__global__ void __launch_bounds__(256, 1) k_mma(
    const bf16* __restrict__ Ah, const bf16* __restrict__ Al,
    const bf16* __restrict__ Bh, const bf16* __restrict__ Bl,
    const float* __restrict__ bias, const float* __restrict__ res,
    float* __restrict__ Cf, bf16* __restrict__ Chi, bf16* __restrict__ Clo,
    int M, int Nn, int K)
{
    extern __shared__ char smem[];
    uint32_t sbase = smem_u32(smem);
    int tid = threadIdx.x;
    int wid = tid >> 5, lane = tid & 31;
    int wm = wid >> 2, wn = wid & 3;          // warp grid 2(m) x 4(n)
    int rowBase = blockIdx.y * 128;
    int colBase = blockIdx.x * 128;

    float acc[4][4][4];                        // [mtile16][ntile8][c0..c3]
#pragma unroll
    for (int a = 0; a < 4; a++)
#pragma unroll
        for (int b = 0; b < 4; b++)
#pragma unroll
            for (int c = 0; c < 4; c++) acc[a][b][c] = 0.f;

    int nChunks = (K + 63) / 64;

    // prologue: chunk 0 -> buffer 0
    load_plane(Ah, rowBase, M,  K, 0, smem);
    load_plane(Al, rowBase, M,  K, 0, smem + TILE_BYTES);
    load_plane(Bh, colBase, Nn, K, 0, smem + 2 * TILE_BYTES);
    load_plane(Bl, colBase, Nn, K, 0, smem + 3 * TILE_BYTES);
    __syncthreads();

    // per-lane ldmatrix offsets (within a plane)
    int aRow = wm * 64 + (lane & 15);          // + mt*16
    int aKb  = (lane >> 4) << 4;               // 0 or 16 bytes
    int bRow = wn * 32 + (lane & 7);           // + nt*8
    int bKb  = ((lane >> 3) & 1) << 4;         // 0 or 16 bytes

    for (int c = 0; c < nChunks; c++) {
        int b = c & 1;
        if (c + 1 < nChunks) {
            char* nb = smem + (b ^ 1) * BUF_BYTES;
            int kb = (c + 1) * 64;
            load_plane(Ah, rowBase, M,  K, kb, nb);
            load_plane(Al, rowBase, M,  K, kb, nb + TILE_BYTES);
            load_plane(Bh, colBase, Nn, K, kb, nb + 2 * TILE_BYTES);
            load_plane(Bl, colBase, Nn, K, kb, nb + 3 * TILE_BYTES);
        }
        uint32_t pA_h = sbase + b * BUF_BYTES;
        uint32_t pA_l = pA_h + TILE_BYTES;
        uint32_t pB_h = pA_h + 2 * TILE_BYTES;
        uint32_t pB_l = pA_h + 3 * TILE_BYTES;

        int rem = K - c * 64;
        int ksteps = rem >= 64 ? 4 : (rem + 15) >> 4;
        for (int ks = 0; ks < ksteps; ks++) {
            int kbyte = ks * 32;
            uint32_t ah[4][4], al[4][4], bh[4][2], bl[4][2];
#pragma unroll
            for (int mt = 0; mt < 4; mt++) {
                int off = (aRow + mt * 16) * 128 + kbyte + aKb;
                ldsm4(ah[mt], pA_h + SWZ128(off));
                ldsm4(al[mt], pA_l + SWZ128(off));
            }
#pragma unroll
            for (int nt = 0; nt < 4; nt++) {
                int off = (bRow + nt * 8) * 128 + kbyte + bKb;
                ldsm2(bh[nt], pB_h + SWZ128(off));
                ldsm2(bl[nt], pB_l + SWZ128(off));
            }
#pragma unroll
            for (int mt = 0; mt < 4; mt++)
#pragma unroll
                for (int nt = 0; nt < 4; nt++) {
                    mma16816(acc[mt][nt], ah[mt], bh[nt]);
                    mma16816(acc[mt][nt], ah[mt], bl[nt]);
                    mma16816(acc[mt][nt], al[mt], bh[nt]);
                }
        }
        __syncthreads();
    }

    // ---------------- epilogue ----------------
#pragma unroll
    for (int mt = 0; mt < 4; mt++) {
        int r0 = rowBase + wm * 64 + mt * 16 + (lane >> 2);
#pragma unroll
        for (int half = 0; half < 2; half++) {
            int row = r0 + half * 8;
            if (row >= M) continue;
            int trow = 0;
            if (EPI == 2) {
                int n = row / (Wcfg * Lw);
                int rem2 = row - n * (Wcfg * Lw);
                int w = rem2 / Lw, l = rem2 - w * Lw;
                trow = (n * Tcfg + w + l) * Dcfg;
            }
#pragma unroll
            for (int nt = 0; nt < 4; nt++) {
                int col = colBase + wn * 32 + nt * 8 + ((lane & 3) << 1);
                if (col >= Nn) continue;
                float v0 = acc[mt][nt][half * 2 + 0] + bias[col];
                float v1 = acc[mt][nt][half * 2 + 1] + bias[col + 1];
                if (EPI == 1) {
                    v0 = 0.5f * v0 * (1.f + erff(v0 * 0.70710678118654752440f));
                    v1 = 0.5f * v1 * (1.f + erff(v1 * 0.70710678118654752440f));
                    bf16 h0, l0, h1b, l1b;
                    split32(v0, h0, l0);
                    split32(v1, h1b, l1b);
                    size_t o = (size_t)row * Nn + col;
                    *(__nv_bfloat162*)(Chi + o) = __nv_bfloat162(h0, h1b);
                    *(__nv_bfloat162*)(Clo + o) = __nv_bfloat162(l0, l1b);
                } else {
                    if (EPI == 2) { v0 += res[trow + col]; v1 += res[trow + col + 1]; }
                    if (EPI == 3) {
                        size_t o = (size_t)row * Nn + col;
                        v0 += res[o]; v1 += res[o + 1];
                    }
                    *(float2*)(Cf + (size_t)row * Nn + col) = make_float2(v0, v1);
                }
            }
        }
    }
}

// ---------------- kernel: [N,C,T,V] -> [N,T,D] + PE, emit fp32 + bf16 hi/lo --------
__global__ void k_build_xs(const float* __restrict__ x, const float* __restrict__ pe) {
    int idx = blockIdx.x * 256 + threadIdx.x;
    if (idx >= NT * Dcfg) return;
    int d   = idx % Dcfg;
    int row = idx / Dcfg;
    int t = row % Tcfg, n = row / Tcfg;
    int v = d / Ccfg,   c = d % Ccfg;
    float val = x[((size_t)(n * Ccfg + c) * Tcfg + t) * Vcfg + v] + pe[t * Dcfg + d];
    g_xs[idx] = val;
    split32(val, g_xs_h[idx], g_xs_l[idx]);
}

// ---------------- weight split ----------------
__global__ void k_split(const float* __restrict__ src, bf16* __restrict__ hi,
                        bf16* __restrict__ lo, int n) {
    int i = blockIdx.x * 256 + threadIdx.x;
    if (i < n) split32(src[i], hi[i], lo[i]);
}

// ---------------- attention: one block per window (L=9, H=2, dh=200) ---------------
__global__ void __launch_bounds__(256) k_attn() {
    __shared__ float sbuf[Lw * 3 * Dcfg];     // 9 x 1200 = 43.2 KB
    __shared__ float ssc[2 * Lw * Lw];
    int b = blockIdx.x;
    int n = b / Wcfg, w = b - n * Wcfg;
    int tid = threadIdx.x;

    for (int idx = tid; idx < Lw * 3 * Dcfg; idx += 256) {
        int t = idx / (3 * Dcfg), col = idx - t * (3 * Dcfg);
        sbuf[idx] = g_qkv[(size_t)(n * Tcfg + w + t) * (3 * Dcfg) + col];
    }
    __syncthreads();

    int wid = tid >> 5, lane = tid & 31;
    for (int p = wid; p < 162; p += 8) {
        int h = p / 81, rem = p - h * 81;
        int i = rem / 9, j = rem - i * 9;
        const float* qp = &sbuf[i * 1200 + h * DH];
        const float* kp = &sbuf[j * 1200 + Dcfg + h * DH];
        float s = 0.f;
        for (int d = lane; d < DH; d += 32) s += qp[d] * kp[d];
#pragma unroll
        for (int o = 16; o; o >>= 1) s += __shfl_xor_sync(0xffffffffu, s, o);
        if (lane == 0) ssc[p] = s * 0.07071067811865475f;   // 1/sqrt(200)
    }
    __syncthreads();

    if (tid < 18) {
        float* r = &ssc[tid * 9];
        float m = r[0];
#pragma unroll
        for (int j = 1; j < 9; j++) m = fmaxf(m, r[j]);
        float s = 0.f;
#pragma unroll
        for (int j = 0; j < 9; j++) { float e = expf(r[j] - m); r[j] = e; s += e; }
        float inv = 1.f / s;
#pragma unroll
        for (int j = 0; j < 9; j++) r[j] *= inv;
    }
    __syncthreads();

    size_t obase = (size_t)b * Lw * Dcfg;
    for (int idx = tid; idx < Lw * Dcfg; idx += 256) {
        int i = idx / Dcfg, c = idx - i * Dcfg;
        int h = c / DH;
        const float* att = &ssc[(h * 9 + i) * 9];
        float s = 0.f;
#pragma unroll
        for (int j = 0; j < 9; j++) s += att[j] * sbuf[j * 1200 + 2 * Dcfg + c];
        split32(s, g_attn_h[obase + idx], g_attn_l[obase + idx]);
    }
}

// ---------------- layernorm over rows of 400, in place; optional bf16 planes -------
__global__ void __launch_bounds__(128) k_ln(float* __restrict__ X,
                                            const float* __restrict__ g,
                                            const float* __restrict__ bb,
                                            bf16* __restrict__ hi,
                                            bf16* __restrict__ lo) {
    int row = blockIdx.x;
    float* xr = X + (size_t)row * Dcfg;
    int tid = threadIdx.x;
    float s = 0.f, s2 = 0.f;
    for (int i = tid; i < Dcfg; i += 128) { float v = xr[i]; s += v; s2 += v * v; }
#pragma unroll
    for (int o = 16; o; o >>= 1) {
        s  += __shfl_xor_sync(0xffffffffu, s, o);
        s2 += __shfl_xor_sync(0xffffffffu, s2, o);
    }
    __shared__ float sh[10];
    int wid = tid >> 5, lane = tid & 31;
    if (lane == 0) { sh[wid] = s; sh[4 + wid] = s2; }
    __syncthreads();
    if (tid == 0) {
        float ts  = sh[0] + sh[1] + sh[2] + sh[3];
        float ts2 = sh[4] + sh[5] + sh[6] + sh[7];
        float mu  = ts * (1.f / Dcfg);
        float var = ts2 * (1.f / Dcfg) - mu * mu;
        sh[8] = mu; sh[9] = rsqrtf(var + 1e-5f);
    }
    __syncthreads();
    float mu = sh[8], rstd = sh[9];
    for (int i = tid; i < Dcfg; i += 128) {
        float v = (xr[i] - mu) * rstd * g[i] + bb[i];
        xr[i] = v;
        if (hi) {
            size_t o = (size_t)row * Dcfg + i;
            split32(v, hi[o], lo[o]);
        }
    }
}

// ---------------- overlap-add as gather + output permute [N,T,D]->[N,C,T,V] --------
__global__ void k_gather(float* __restrict__ out) {
    int idx = blockIdx.x * 256 + threadIdx.x;
    if (idx >= NT * Dcfg) return;
    int d = idx % Dcfg;
    int r = idx / Dcfg;
    int t = r % Tcfg, n = r / Tcfg;
    float acc = 0.f;
    int lmax = t < 8 ? t : 8;
    for (int l = 0; l <= lmax; l++) {
        int w0 = 2 * (t - l);
        if (w0 < Wcfg) {
            acc += g_h2[((size_t)((n * Wcfg + w0) * Lw + l)) * Dcfg + d];
            if (w0 + 1 < Wcfg)
                acc += g_h2[((size_t)((n * Wcfg + w0 + 1) * Lw + l)) * Dcfg + d];
        }
    }
    int v = d / Ccfg, c = d % Ccfg;
    out[((size_t)(n * Ccfg + c) * Tcfg + t) * Vcfg + v] = acc;
}

// ---------------- launch ----------------
extern "C" void kernel_launch(void* const* d_in, const int* in_sizes, int n_in,
                              void* d_out, int out_size) {
    (void)in_sizes; (void)n_in; (void)out_size;
    const float* x     = (const float*)d_in[0];
    const float* pe    = (const float*)d_in[1];
    const float* w_in  = (const float*)d_in[2];
    const float* b_in  = (const float*)d_in[3];
    const float* w_out = (const float*)d_in[4];
    const float* b_out = (const float*)d_in[5];
    const float* w1    = (const float*)d_in[6];
    const float* b1    = (const float*)d_in[7];
    const float* w2    = (const float*)d_in[8];
    const float* b2    = (const float*)d_in[9];
    const float* ln1g  = (const float*)d_in[10];
    const float* ln1b  = (const float*)d_in[11];
    const float* ln2g  = (const float*)d_in[12];
    const float* ln2b  = (const float*)d_in[13];
    float* out = (float*)d_out;

    float *xs, *qkv, *h1, *h2;
    bf16 *xsh, *xsl, *winh, *winl, *wouth, *woutl, *w1h, *w1l, *w2h, *w2l;
    bf16 *atth, *attl, *h1h, *h1l, *ffh, *ffl;
    cudaGetSymbolAddress((void**)&xs,    g_xs);
    cudaGetSymbolAddress((void**)&qkv,   g_qkv);
    cudaGetSymbolAddress((void**)&h1,    g_h1);
    cudaGetSymbolAddress((void**)&h2,    g_h2);
    cudaGetSymbolAddress((void**)&xsh,   g_xs_h);
    cudaGetSymbolAddress((void**)&xsl,   g_xs_l);
    cudaGetSymbolAddress((void**)&winh,  g_win_h);
    cudaGetSymbolAddress((void**)&winl,  g_win_l);
    cudaGetSymbolAddress((void**)&wouth, g_wout_h);
    cudaGetSymbolAddress((void**)&woutl, g_wout_l);
    cudaGetSymbolAddress((void**)&w1h,   g_w1_h);
    cudaGetSymbolAddress((void**)&w1l,   g_w1_l);
    cudaGetSymbolAddress((void**)&w2h,   g_w2_h);
    cudaGetSymbolAddress((void**)&w2l,   g_w2_l);
    cudaGetSymbolAddress((void**)&atth,  g_attn_h);
    cudaGetSymbolAddress((void**)&attl,  g_attn_l);
    cudaGetSymbolAddress((void**)&h1h,   g_h1_h);
    cudaGetSymbolAddress((void**)&h1l,   g_h1_l);
    cudaGetSymbolAddress((void**)&ffh,   g_ff_h);
    cudaGetSymbolAddress((void**)&ffl,   g_ff_l);

    cudaFuncSetAttribute(k_mma<0>, cudaFuncAttributeMaxDynamicSharedMemorySize, SMEM_TOTAL);
    cudaFuncSetAttribute(k_mma<1>, cudaFuncAttributeMaxDynamicSharedMemorySize, SMEM_TOTAL);
    cudaFuncSetAttribute(k_mma<2>, cudaFuncAttributeMaxDynamicSharedMemorySize, SMEM_TOTAL);
    cudaFuncSetAttribute(k_mma<3>, cudaFuncAttributeMaxDynamicSharedMemorySize, SMEM_TOTAL);

    // 1. permute + PE (+ bf16 split)
    k_build_xs<<<(NT * Dcfg + 255) / 256, 256>>>(x, pe);

    // weight splits
    k_split<<<(3 * Dcfg * Dcfg + 255) / 256, 256>>>(w_in,  winh,  winl,  3 * Dcfg * Dcfg);
    k_split<<<(Dcfg * Dcfg + 255) / 256, 256>>>(w_out, wouth, woutl, Dcfg * Dcfg);
    k_split<<<(FFc * Dcfg + 255) / 256, 256>>>(w1, w1h, w1l, FFc * Dcfg);
    k_split<<<(Dcfg * FFc + 255) / 256, 256>>>(w2, w2h, w2l, Dcfg * FFc);

    // 2. per-token QKV: [4800,400] @ [1200,400]^T -> fp32
    {
        dim3 g((3 * Dcfg + 127) / 128, (NT + 127) / 128);
        k_mma<0><<<g, 256, SMEM_TOTAL>>>(xsh, xsl, winh, winl, b_in, nullptr,
                                         qkv, nullptr, nullptr, NT, 3 * Dcfg, Dcfg);
    }

    // 3. windowed attention -> bf16 hi/lo planes
    k_attn<<<NW, 256>>>();

    // 4. out-proj + residual (gathered xs) -> h1 fp32, then LN1 (+ planes)
    {
        dim3 g((Dcfg + 127) / 128, (M2 + 127) / 128);
        k_mma<2><<<g, 256, SMEM_TOTAL>>>(atth, attl, wouth, woutl, b_out, xs,
                                         h1, nullptr, nullptr, M2, Dcfg, Dcfg);
    }
    k_ln<<<M2, 128>>>(h1, ln1g, ln1b, h1h, h1l);

    // 5. FFN up + gelu -> ff bf16 planes (no fp32 intermediate)
    {
        dim3 g((FFc + 127) / 128, (M2 + 127) / 128);
        k_mma<1><<<g, 256, SMEM_TOTAL>>>(h1h, h1l, w1h, w1l, b1, nullptr,
                                         nullptr, ffh, ffl, M2, FFc, Dcfg);
    }
    // 6. FFN down + residual -> h2 fp32, then LN2
    {
        dim3 g((Dcfg + 127) / 128, (M2 + 127) / 128);
        k_mma<3><<<g, 256, SMEM_TOTAL>>>(ffh, ffl, w2h, w2l, b2, h1,
                                         h2, nullptr, nullptr, M2, Dcfg, FFc);
    }
    k_ln<<<M2, 128>>>(h2, ln2g, ln2b, nullptr, nullptr);

    // 7. overlap-add gather + output permute
    k_gather<<<(NT * Dcfg + 255) / 256, 256>>>(out);
}

// round 9
// speedup vs baseline: 1.7498x; 1.1191x over previous
#include <cuda_runtime.h>
#include <cuda_bf16.h>
#include <cstdint>
#include <math.h>

// ---------------- problem constants ----------------
#define Ncfg 16
#define Ccfg 16
#define Tcfg 300
#define Vcfg 25
#define Dcfg 400           // C*V
#define DH   200           // head dim (H=2)
#define FFc  1600
#define Lw   9
#define Wcfg 291           // T - L
#define NW   (Ncfg*Wcfg)   // 4656 windows
#define M2   (NW*Lw)       // 41904 window rows
#define NT   (Ncfg*Tcfg)   // 4800 tokens

typedef __nv_bfloat16 bf16;

// ---------------- scratch (device globals; no allocs allowed) ----------------
__device__ float g_xs   [NT * Dcfg];
__device__ bf16  g_xs_h [NT * Dcfg];
__device__ bf16  g_xs_l [NT * Dcfg];
__device__ bf16  g_win_h[3 * Dcfg * Dcfg];
__device__ bf16  g_win_l[3 * Dcfg * Dcfg];
__device__ bf16  g_wout_h[Dcfg * Dcfg];
__device__ bf16  g_wout_l[Dcfg * Dcfg];
__device__ bf16  g_w1_h [FFc * Dcfg];
__device__ bf16  g_w1_l [FFc * Dcfg];
__device__ bf16  g_w2_h [Dcfg * FFc];
__device__ bf16  g_w2_l [Dcfg * FFc];
__device__ float g_qkv  [NT * 3 * Dcfg];
__device__ bf16  g_attn_h[M2 * Dcfg];
__device__ bf16  g_attn_l[M2 * Dcfg];
__device__ float g_h1   [M2 * Dcfg];
__device__ bf16  g_h1_h [M2 * Dcfg];
__device__ bf16  g_h1_l [M2 * Dcfg];
__device__ bf16  g_ff_h [(size_t)M2 * FFc];
__device__ bf16  g_ff_l [(size_t)M2 * FFc];
__device__ float g_h2   [M2 * Dcfg];

// ---------------- helpers ----------------
__device__ __forceinline__ uint32_t smem_u32(const void* p) {
    uint32_t a;
    asm("{ .reg .u64 t; cvta.to.shared.u64 t, %1; cvt.u32.u64 %0, t; }" : "=r"(a) : "l"(p));
    return a;
}
#define SWZ128(o) ((o) ^ (((o) >> 3) & 0x70))

__device__ __forceinline__ void ldsm4(uint32_t* r, uint32_t a) {
    asm volatile("ldmatrix.sync.aligned.m8n8.x4.shared.b16 {%0,%1,%2,%3}, [%4];"
        : "=r"(r[0]), "=r"(r[1]), "=r"(r[2]), "=r"(r[3]) : "r"(a));
}
// mma m16n8k16 row.col f32 += bf16*bf16
__device__ __forceinline__ void mma16816(float* c, const uint32_t* a, const uint32_t* b) {
    asm volatile("mma.sync.aligned.m16n8k16.row.col.f32.bf16.bf16.f32 "
        "{%0,%1,%2,%3}, {%4,%5,%6,%7}, {%8,%9}, {%0,%1,%2,%3};"
        : "+f"(c[0]), "+f"(c[1]), "+f"(c[2]), "+f"(c[3])
        : "r"(a[0]), "r"(a[1]), "r"(a[2]), "r"(a[3]), "r"(b[0]), "r"(b[1]));
}
#define CP_COMMIT() asm volatile("cp.async.commit_group;" ::: "memory")
#define CP_WAIT1()  asm volatile("cp.async.wait_group 1;" ::: "memory")

__device__ __forceinline__ void split32(float v, bf16& h, bf16& l) {
    h = __float2bfloat16(v);
    l = __float2bfloat16(v - __bfloat162float(h));
}

// ---------------- smem: 4 planes (Ah, Al, Bh, Bl) x 3 pipeline stages ----------------
#define TILE_BYTES 16384                 // 128 rows x 128B (64 bf16)
#define BUF_BYTES  (4 * TILE_BYTES)      // 64 KB / stage
#define STAGES     3
#define SMEM_TOTAL (STAGES * BUF_BYTES)  // 196608

// async-copy one 128x64 bf16 plane into swizzled smem (256 threads, 16B granules)
__device__ __forceinline__ void load_plane_cp(const bf16* __restrict__ G, int rowBase,
                                              int rows, int K, int kbase, uint32_t sdst) {
    int t = threadIdx.x;
    int r = t >> 1, half = t & 1;
    int gr = rowBase + r;
    bool rok = gr < rows;
    const bf16* gp = G + (size_t)(rok ? gr : 0) * K;
#pragma unroll
    for (int i = 0; i < 4; i++) {
        int kc = kbase + half * 32 + i * 8;
        int boff = r * 128 + half * 64 + i * 16;
        uint32_t dst = sdst + SWZ128(boff);
        int srcsz = (rok && kc + 8 <= K) ? 16 : 0;   // K is a multiple of 8
        asm volatile("cp.async.cg.shared.global [%0], [%1], 16, %2;"
                     :: "r"(dst), "l"(gp + kc), "r"(srcsz));
    }
}

// ---------------- HMMA GEMM: C[M,Nn] = A[M,K] @ B[Nn,K]^T + bias, epilogues --------
// A,B as split bf16 planes.  acc += Ah*Bh + Ah*Bl + Al*Bh  (fp32 accumulate)
// EPI: 0 bias->fp32 | 1 bias+gelu->bf16 hi/lo planes | 2 bias+res(gathered xs)->fp32
//      3 bias+res(row)->fp32
template <int EPI>
__global__ void __launch_bounds__(256, 1) k_mma(
    const bf16* __restrict__ Ah, const bf16* __restrict__ Al,
    const bf16* __restrict__ Bh, const bf16* __restrict__ Bl,
    const float* __restrict__ bias, const float* __restrict__ res,
    float* __restrict__ Cf, bf16* __restrict__ Chi, bf16* __restrict__ Clo,
    int M, int Nn, int K)
{
    extern __shared__ char smem[];
    uint32_t sbase = smem_u32(smem);
    int tid = threadIdx.x;
    int wid = tid >> 5, lane = tid & 31;
    int wm = wid >> 2, wn = wid & 3;          // warp grid 2(m) x 4(n)
    int rowBase = blockIdx.y * 128;
    int colBase = blockIdx.x * 128;

    float acc[4][4][4];                        // [mtile16][ntile8][c0..c3]
#pragma unroll
    for (int a = 0; a < 4; a++)
#pragma unroll
        for (int b = 0; b < 4; b++)
#pragma unroll
            for (int c = 0; c < 4; c++) acc[a][b][c] = 0.f;

    int nChunks = (K + 63) / 64;

    // issue one chunk's 4 planes into stage s (no commit)
    auto issue = [&](int c, int s) {
        uint32_t sb = sbase + s * BUF_BYTES;
        int kb = c * 64;
        load_plane_cp(Ah, rowBase, M,  K, kb, sb);
        load_plane_cp(Al, rowBase, M,  K, kb, sb + TILE_BYTES);
        load_plane_cp(Bh, colBase, Nn, K, kb, sb + 2 * TILE_BYTES);
        load_plane_cp(Bl, colBase, Nn, K, kb, sb + 3 * TILE_BYTES);
    };

    // prologue: two groups always committed (empty groups complete instantly)
    issue(0, 0);
    CP_COMMIT();
    if (nChunks > 1) issue(1, 1);
    CP_COMMIT();

    // per-lane ldmatrix offsets (within a plane)
    int aRow = wm * 64 + (lane & 15);                      // + mt*16
    int aKb  = (lane >> 4) << 4;                           // 0 or 16 bytes
    int bRowP = wn * 32 + ((lane >> 4) << 3) + (lane & 7); // + pair*16
    int bKb  = ((lane >> 3) & 1) << 4;                     // 0 or 16 bytes

    for (int c = 0; c < nChunks; c++) {
        CP_WAIT1();                 // chunk c resident
        __syncthreads();            // visible to all warps; stage (c+2)%3 free
        if (c + 2 < nChunks) issue(c + 2, (c + 2) % STAGES);
        CP_COMMIT();                // exactly one group per iteration

        uint32_t pA_h = sbase + (c % STAGES) * BUF_BYTES;
        uint32_t pA_l = pA_h + TILE_BYTES;
        uint32_t pB_h = pA_h + 2 * TILE_BYTES;
        uint32_t pB_l = pA_h + 3 * TILE_BYTES;

        int rem = K - c * 64;
        int ksteps = rem >= 64 ? 4 : (rem + 15) >> 4;
        for (int ks = 0; ks < ksteps; ks++) {
            int kbyte = ks * 32;
            uint32_t ah[4][4], al[4][4], bh2[2][4], bl2[2][4];
#pragma unroll
            for (int mt = 0; mt < 4; mt++) {
                int off = (aRow + mt * 16) * 128 + kbyte + aKb;
                ldsm4(ah[mt], pA_h + SWZ128(off));
                ldsm4(al[mt], pA_l + SWZ128(off));
            }
#pragma unroll
            for (int p = 0; p < 2; p++) {       // each x4 covers two n8-tiles
                int off = (bRowP + p * 16) * 128 + kbyte + bKb;
                ldsm4(bh2[p], pB_h + SWZ128(off));
                ldsm4(bl2[p], pB_l + SWZ128(off));
            }
#pragma unroll
            for (int mt = 0; mt < 4; mt++)
#pragma unroll
                for (int p = 0; p < 2; p++) {
                    mma16816(acc[mt][2 * p],     ah[mt], bh2[p]);
                    mma16816(acc[mt][2 * p],     ah[mt], bl2[p]);
                    mma16816(acc[mt][2 * p],     al[mt], bh2[p]);
                    mma16816(acc[mt][2 * p + 1], ah[mt], bh2[p] + 2);
                    mma16816(acc[mt][2 * p + 1], ah[mt], bl2[p] + 2);
                    mma16816(acc[mt][2 * p + 1], al[mt], bh2[p] + 2);
                }
        }
        __syncthreads();
    }

    // ---------------- epilogue ----------------
#pragma unroll
    for (int mt = 0; mt < 4; mt++) {
        int r0 = rowBase + wm * 64 + mt * 16 + (lane >> 2);
#pragma unroll
        for (int half = 0; half < 2; half++) {
            int row = r0 + half * 8;
            if (row >= M) continue;
            int trow = 0;
            if (EPI == 2) {
                int n = row / (Wcfg * Lw);
                int rem2 = row - n * (Wcfg * Lw);
                int w = rem2 / Lw, l = rem2 - w * Lw;
                trow = (n * Tcfg + w + l) * Dcfg;
            }
#pragma unroll
            for (int nt = 0; nt < 4; nt++) {
                int col = colBase + wn * 32 + nt * 8 + ((lane & 3) << 1);
                if (col >= Nn) continue;
                float v0 = acc[mt][nt][half * 2 + 0] + bias[col];
                float v1 = acc[mt][nt][half * 2 + 1] + bias[col + 1];
                if (EPI == 1) {
                    v0 = 0.5f * v0 * (1.f + erff(v0 * 0.70710678118654752440f));
                    v1 = 0.5f * v1 * (1.f + erff(v1 * 0.70710678118654752440f));
                    bf16 h0, l0, h1b, l1b;
                    split32(v0, h0, l0);
                    split32(v1, h1b, l1b);
                    size_t o = (size_t)row * Nn + col;
                    *(__nv_bfloat162*)(Chi + o) = __nv_bfloat162(h0, h1b);
                    *(__nv_bfloat162*)(Clo + o) = __nv_bfloat162(l0, l1b);
                } else {
                    if (EPI == 2) { v0 += res[trow + col]; v1 += res[trow + col + 1]; }
                    if (EPI == 3) {
                        size_t o = (size_t)row * Nn + col;
                        v0 += res[o]; v1 += res[o + 1];
                    }
                    *(float2*)(Cf + (size_t)row * Nn + col) = make_float2(v0, v1);
                }
            }
        }
    }
}

// ---------------- kernel: [N,C,T,V] -> [N,T,D] + PE, emit fp32 + bf16 hi/lo --------
__global__ void k_build_xs(const float* __restrict__ x, const float* __restrict__ pe) {
    int idx = blockIdx.x * 256 + threadIdx.x;
    if (idx >= NT * Dcfg) return;
    int d   = idx % Dcfg;
    int row = idx / Dcfg;
    int t = row % Tcfg, n = row / Tcfg;
    int v = d / Ccfg,   c = d % Ccfg;
    float val = x[((size_t)(n * Ccfg + c) * Tcfg + t) * Vcfg + v] + pe[t * Dcfg + d];
    g_xs[idx] = val;
    split32(val, g_xs_h[idx], g_xs_l[idx]);
}

// ---------------- weight split ----------------
__global__ void k_split(const float* __restrict__ src, bf16* __restrict__ hi,
                        bf16* __restrict__ lo, int n) {
    int i = blockIdx.x * 256 + threadIdx.x;
    if (i < n) split32(src[i], hi[i], lo[i]);
}

// ---------------- attention: one block per window (L=9, H=2, dh=200) ---------------
__global__ void __launch_bounds__(256) k_attn() {
    __shared__ float sbuf[Lw * 3 * Dcfg];     // 9 x 1200 = 43.2 KB
    __shared__ float ssc[2 * Lw * Lw];
    int b = blockIdx.x;
    int n = b / Wcfg, w = b - n * Wcfg;
    int tid = threadIdx.x;

    for (int idx = tid; idx < Lw * 3 * Dcfg; idx += 256) {
        int t = idx / (3 * Dcfg), col = idx - t * (3 * Dcfg);
        sbuf[idx] = g_qkv[(size_t)(n * Tcfg + w + t) * (3 * Dcfg) + col];
    }
    __syncthreads();

    int wid = tid >> 5, lane = tid & 31;
    for (int p = wid; p < 162; p += 8) {
        int h = p / 81, rem = p - h * 81;
        int i = rem / 9, j = rem - i * 9;
        const float* qp = &sbuf[i * 1200 + h * DH];
        const float* kp = &sbuf[j * 1200 + Dcfg + h * DH];
        float s = 0.f;
        for (int d = lane; d < DH; d += 32) s += qp[d] * kp[d];
#pragma unroll
        for (int o = 16; o; o >>= 1) s += __shfl_xor_sync(0xffffffffu, s, o);
        if (lane == 0) ssc[p] = s * 0.07071067811865475f;   // 1/sqrt(200)
    }
    __syncthreads();

    if (tid < 18) {
        float* r = &ssc[tid * 9];
        float m = r[0];
#pragma unroll
        for (int j = 1; j < 9; j++) m = fmaxf(m, r[j]);
        float s = 0.f;
#pragma unroll
        for (int j = 0; j < 9; j++) { float e = expf(r[j] - m); r[j] = e; s += e; }
        float inv = 1.f / s;
#pragma unroll
        for (int j = 0; j < 9; j++) r[j] *= inv;
    }
    __syncthreads();

    size_t obase = (size_t)b * Lw * Dcfg;
    for (int idx = tid; idx < Lw * Dcfg; idx += 256) {
        int i = idx / Dcfg, c = idx - i * Dcfg;
        int h = c / DH;
        const float* att = &ssc[(h * 9 + i) * 9];
        float s = 0.f;
#pragma unroll
        for (int j = 0; j < 9; j++) s += att[j] * sbuf[j * 1200 + 2 * Dcfg + c];
        split32(s, g_attn_h[obase + idx], g_attn_l[obase + idx]);
    }
}

// ---------------- layernorm over rows of 400, in place; optional bf16 planes -------
__global__ void __launch_bounds__(128) k_ln(float* __restrict__ X,
                                            const float* __restrict__ g,
                                            const float* __restrict__ bb,
                                            bf16* __restrict__ hi,
                                            bf16* __restrict__ lo) {
    int row = blockIdx.x;
    float* xr = X + (size_t)row * Dcfg;
    int tid = threadIdx.x;
    float s = 0.f, s2 = 0.f;
    for (int i = tid; i < Dcfg; i += 128) { float v = xr[i]; s += v; s2 += v * v; }
#pragma unroll
    for (int o = 16; o; o >>= 1) {
        s  += __shfl_xor_sync(0xffffffffu, s, o);
        s2 += __shfl_xor_sync(0xffffffffu, s2, o);
    }
    __shared__ float sh[10];
    int wid = tid >> 5, lane = tid & 31;
    if (lane == 0) { sh[wid] = s; sh[4 + wid] = s2; }
    __syncthreads();
    if (tid == 0) {
        float ts  = sh[0] + sh[1] + sh[2] + sh[3];
        float ts2 = sh[4] + sh[5] + sh[6] + sh[7];
        float mu  = ts * (1.f / Dcfg);
        float var = ts2 * (1.f / Dcfg) - mu * mu;
        sh[8] = mu; sh[9] = rsqrtf(var + 1e-5f);
    }
    __syncthreads();
    float mu = sh[8], rstd = sh[9];
    for (int i = tid; i < Dcfg; i += 128) {
        float v = (xr[i] - mu) * rstd * g[i] + bb[i];
        xr[i] = v;
        if (hi) {
            size_t o = (size_t)row * Dcfg + i;
            split32(v, hi[o], lo[o]);
        }
    }
}

// ---------------- overlap-add as gather + output permute [N,T,D]->[N,C,T,V] --------
__global__ void k_gather(float* __restrict__ out) {
    int idx = blockIdx.x * 256 + threadIdx.x;
    if (idx >= NT * Dcfg) return;
    int d = idx % Dcfg;
    int r = idx / Dcfg;
    int t = r % Tcfg, n = r / Tcfg;
    float acc = 0.f;
    int lmax = t < 8 ? t : 8;
    for (int l = 0; l <= lmax; l++) {
        int w0 = 2 * (t - l);
        if (w0 < Wcfg) {
            acc += g_h2[((size_t)((n * Wcfg + w0) * Lw + l)) * Dcfg + d];
            if (w0 + 1 < Wcfg)
                acc += g_h2[((size_t)((n * Wcfg + w0 + 1) * Lw + l)) * Dcfg + d];
        }
    }
    int v = d / Ccfg, c = d % Ccfg;
    out[((size_t)(n * Ccfg + c) * Tcfg + t) * Vcfg + v] = acc;
}

// ---------------- launch ----------------
extern "C" void kernel_launch(void* const* d_in, const int* in_sizes, int n_in,
                              void* d_out, int out_size) {
    (void)in_sizes; (void)n_in; (void)out_size;
    const float* x     = (const float*)d_in[0];
    const float* pe    = (const float*)d_in[1];
    const float* w_in  = (const float*)d_in[2];
    const float* b_in  = (const float*)d_in[3];
    const float* w_out = (const float*)d_in[4];
    const float* b_out = (const float*)d_in[5];
    const float* w1    = (const float*)d_in[6];
    const float* b1    = (const float*)d_in[7];
    const float* w2    = (const float*)d_in[8];
    const float* b2    = (const float*)d_in[9];
    const float* ln1g  = (const float*)d_in[10];
    const float* ln1b  = (const float*)d_in[11];
    const float* ln2g  = (const float*)d_in[12];
    const float* ln2b  = (const float*)d_in[13];
    float* out = (float*)d_out;

    float *xs, *qkv, *h1, *h2;
    bf16 *xsh, *xsl, *winh, *winl, *wouth, *woutl, *w1h, *w1l, *w2h, *w2l;
    bf16 *atth, *attl, *h1h, *h1l, *ffh, *ffl;
    cudaGetSymbolAddress((void**)&xs,    g_xs);
    cudaGetSymbolAddress((void**)&qkv,   g_qkv);
    cudaGetSymbolAddress((void**)&h1,    g_h1);
    cudaGetSymbolAddress((void**)&h2,    g_h2);
    cudaGetSymbolAddress((void**)&xsh,   g_xs_h);
    cudaGetSymbolAddress((void**)&xsl,   g_xs_l);
    cudaGetSymbolAddress((void**)&winh,  g_win_h);
    cudaGetSymbolAddress((void**)&winl,  g_win_l);
    cudaGetSymbolAddress((void**)&wouth, g_wout_h);
    cudaGetSymbolAddress((void**)&woutl, g_wout_l);
    cudaGetSymbolAddress((void**)&w1h,   g_w1_h);
    cudaGetSymbolAddress((void**)&w1l,   g_w1_l);
    cudaGetSymbolAddress((void**)&w2h,   g_w2_h);
    cudaGetSymbolAddress((void**)&w2l,   g_w2_l);
    cudaGetSymbolAddress((void**)&atth,  g_attn_h);
    cudaGetSymbolAddress((void**)&attl,  g_attn_l);
    cudaGetSymbolAddress((void**)&h1h,   g_h1_h);
    cudaGetSymbolAddress((void**)&h1l,   g_h1_l);
    cudaGetSymbolAddress((void**)&ffh,   g_ff_h);
    cudaGetSymbolAddress((void**)&ffl,   g_ff_l);

    cudaFuncSetAttribute(k_mma<0>, cudaFuncAttributeMaxDynamicSharedMemorySize, SMEM_TOTAL);
    cudaFuncSetAttribute(k_mma<1>, cudaFuncAttributeMaxDynamicSharedMemorySize, SMEM_TOTAL);
    cudaFuncSetAttribute(k_mma<2>, cudaFuncAttributeMaxDynamicSharedMemorySize, SMEM_TOTAL);
    cudaFuncSetAttribute(k_mma<3>, cudaFuncAttributeMaxDynamicSharedMemorySize, SMEM_TOTAL);

    // 1. permute + PE (+ bf16 split)
    k_build_xs<<<(NT * Dcfg + 255) / 256, 256>>>(x, pe);

    // weight splits
    k_split<<<(3 * Dcfg * Dcfg + 255) / 256, 256>>>(w_in,  winh,  winl,  3 * Dcfg * Dcfg);
    k_split<<<(Dcfg * Dcfg + 255) / 256, 256>>>(w_out, wouth, woutl, Dcfg * Dcfg);
    k_split<<<(FFc * Dcfg + 255) / 256, 256>>>(w1, w1h, w1l, FFc * Dcfg);
    k_split<<<(Dcfg * FFc + 255) / 256, 256>>>(w2, w2h, w2l, Dcfg * FFc);

    // 2. per-token QKV: [4800,400] @ [1200,400]^T -> fp32
    {
        dim3 g((3 * Dcfg + 127) / 128, (NT + 127) / 128);
        k_mma<0><<<g, 256, SMEM_TOTAL>>>(xsh, xsl, winh, winl, b_in, nullptr,
                                         qkv, nullptr, nullptr, NT, 3 * Dcfg, Dcfg);
    }

    // 3. windowed attention -> bf16 hi/lo planes
    k_attn<<<NW, 256>>>();

    // 4. out-proj + residual (gathered xs) -> h1 fp32, then LN1 (+ planes)
    {
        dim3 g((Dcfg + 127) / 128, (M2 + 127) / 128);
        k_mma<2><<<g, 256, SMEM_TOTAL>>>(atth, attl, wouth, woutl, b_out, xs,
                                         h1, nullptr, nullptr, M2, Dcfg, Dcfg);
    }
    k_ln<<<M2, 128>>>(h1, ln1g, ln1b, h1h, h1l);

    // 5. FFN up + gelu -> ff bf16 planes (no fp32 intermediate)
    {
        dim3 g((FFc + 127) / 128, (M2 + 127) / 128);
        k_mma<1><<<g, 256, SMEM_TOTAL>>>(h1h, h1l, w1h, w1l, b1, nullptr,
                                         nullptr, ffh, ffl, M2, FFc, Dcfg);
    }
    // 6. FFN down + residual -> h2 fp32, then LN2
    {
        dim3 g((Dcfg + 127) / 128, (M2 + 127) / 128);
        k_mma<3><<<g, 256, SMEM_TOTAL>>>(ffh, ffl, w2h, w2l, b2, h1,
                                         h2, nullptr, nullptr, M2, Dcfg, FFc);
    }
    k_ln<<<M2, 128>>>(h2, ln2g, ln2b, nullptr, nullptr);

    // 7. overlap-add gather + output permute
    k_gather<<<(NT * Dcfg + 255) / 256, 256>>>(out);
}

// round 11
// speedup vs baseline: 2.0079x; 1.1475x over previous
#include <cuda_runtime.h>
#include <cuda_bf16.h>
#include <cstdint>
#include <math.h>

// ---------------- problem constants ----------------
#define Ncfg 16
#define Ccfg 16
#define Tcfg 300
#define Vcfg 25
#define Dcfg 400           // C*V
#define DH   200           // head dim (H=2)
#define FFc  1600
#define Lw   9
#define Wcfg 291           // T - L
#define NW   (Ncfg*Wcfg)   // 4656 windows
#define M2   (NW*Lw)       // 41904 window rows
#define NT   (Ncfg*Tcfg)   // 4800 tokens

typedef __nv_bfloat16 bf16;

// ---------------- scratch (device globals; no allocs allowed) ----------------
__device__ float g_xs   [NT * Dcfg];
__device__ bf16  g_xs_h [NT * Dcfg];
__device__ bf16  g_xs_l [NT * Dcfg];
__device__ bf16  g_win_h[3 * Dcfg * Dcfg];
__device__ bf16  g_win_l[3 * Dcfg * Dcfg];
__device__ bf16  g_wout_h[Dcfg * Dcfg];
__device__ bf16  g_wout_l[Dcfg * Dcfg];
__device__ bf16  g_w1_h [FFc * Dcfg];
__device__ bf16  g_w1_l [FFc * Dcfg];
__device__ bf16  g_w2_h [Dcfg * FFc];
__device__ bf16  g_w2_l [Dcfg * FFc];
__device__ float g_qkv  [NT * 3 * Dcfg];
__device__ bf16  g_attn_h[M2 * Dcfg];
__device__ bf16  g_attn_l[M2 * Dcfg];
__device__ float g_h1   [M2 * Dcfg];
__device__ bf16  g_h1_h [M2 * Dcfg];
__device__ bf16  g_h1_l [M2 * Dcfg];
__device__ bf16  g_ff_h [(size_t)M2 * FFc];
__device__ bf16  g_ff_l [(size_t)M2 * FFc];
__device__ float g_h2   [M2 * Dcfg];

// ---------------- helpers ----------------
__device__ __forceinline__ uint32_t smem_u32(const void* p) {
    uint32_t a;
    asm("{ .reg .u64 t; cvta.to.shared.u64 t, %1; cvt.u32.u64 %0, t; }" : "=r"(a) : "l"(p));
    return a;
}
#define SWZ128(o) ((o) ^ (((o) >> 3) & 0x70))

__device__ __forceinline__ void ldsm4(uint32_t* r, uint32_t a) {
    asm volatile("ldmatrix.sync.aligned.m8n8.x4.shared.b16 {%0,%1,%2,%3}, [%4];"
        : "=r"(r[0]), "=r"(r[1]), "=r"(r[2]), "=r"(r[3]) : "r"(a));
}
// mma m16n8k16 row.col f32 += bf16*bf16
__device__ __forceinline__ void mma16816(float* c, const uint32_t* a, const uint32_t* b) {
    asm volatile("mma.sync.aligned.m16n8k16.row.col.f32.bf16.bf16.f32 "
        "{%0,%1,%2,%3}, {%4,%5,%6,%7}, {%8,%9}, {%0,%1,%2,%3};"
        : "+f"(c[0]), "+f"(c[1]), "+f"(c[2]), "+f"(c[3])
        : "r"(a[0]), "r"(a[1]), "r"(a[2]), "r"(a[3]), "r"(b[0]), "r"(b[1]));
}
#define CP_COMMIT() asm volatile("cp.async.commit_group;" ::: "memory")
#define CP_WAIT1()  asm volatile("cp.async.wait_group 1;" ::: "memory")

__device__ __forceinline__ void split32(float v, bf16& h, bf16& l) {
    h = __float2bfloat16(v);
    l = __float2bfloat16(v - __bfloat162float(h));
}

// ---------------- smem: [Ah 16K][Al 16K][Bh 8K][Bl 8K] x 2 stages = 96 KB ----------
// Block tile 128(M) x 64(N) x 64(K): 2 CTAs/SM for latency hiding via TLP.
#define TILE_A   16384                   // 128 rows x 128B
#define TILE_B   8192                    // 64 rows x 128B
#define BUF_BYTES (2 * TILE_A + 2 * TILE_B)   // 49152
#define STAGES   2
#define SMEM_TOTAL (STAGES * BUF_BYTES)  // 98304

// async-copy a 128x64 bf16 plane (A) into swizzled smem (256 threads)
__device__ __forceinline__ void load_planeA(const bf16* __restrict__ G, int rowBase,
                                            int rows, int K, int kbase, uint32_t sdst) {
    int t = threadIdx.x;
    int r = t >> 1, half = t & 1;
    int gr = rowBase + r;
    bool rok = gr < rows;
    const bf16* gp = G + (size_t)(rok ? gr : 0) * K;
#pragma unroll
    for (int i = 0; i < 4; i++) {
        int kc = kbase + half * 32 + i * 8;
        int boff = r * 128 + half * 64 + i * 16;
        uint32_t dst = sdst + SWZ128(boff);
        int srcsz = (rok && kc + 8 <= K) ? 16 : 0;
        asm volatile("cp.async.cg.shared.global [%0], [%1], 16, %2;"
                     :: "r"(dst), "l"(gp + kc), "r"(srcsz));
    }
}
// async-copy a 64x64 bf16 plane (B) into swizzled smem (256 threads)
__device__ __forceinline__ void load_planeB(const bf16* __restrict__ G, int rowBase,
                                            int rows, int K, int kbase, uint32_t sdst) {
    int t = threadIdx.x;
    int r = t >> 2, q = t & 3;
    int gr = rowBase + r;
    bool rok = gr < rows;
    const bf16* gp = G + (size_t)(rok ? gr : 0) * K;
#pragma unroll
    for (int i = 0; i < 2; i++) {
        int g8 = q + i * 4;                     // granule 0..7
        int kc = kbase + g8 * 8;
        int boff = r * 128 + g8 * 16;
        uint32_t dst = sdst + SWZ128(boff);
        int srcsz = (rok && kc + 8 <= K) ? 16 : 0;
        asm volatile("cp.async.cg.shared.global [%0], [%1], 16, %2;"
                     :: "r"(dst), "l"(gp + kc), "r"(srcsz));
    }
}

// ---------------- HMMA GEMM: C[M,Nn] = A[M,K] @ B[Nn,K]^T + bias, epilogues --------
// A,B as split bf16 planes.  acc += Ah*Bh + Ah*Bl + Al*Bh  (fp32 accumulate)
// EPI: 0 bias->fp32 | 1 bias+gelu->bf16 hi/lo planes | 2 bias+res(gathered xs)->fp32
//      3 bias+res(row)->fp32
template <int EPI>
__global__ void __launch_bounds__(256, 2) k_mma(
    const bf16* __restrict__ Ah, const bf16* __restrict__ Al,
    const bf16* __restrict__ Bh, const bf16* __restrict__ Bl,
    const float* __restrict__ bias, const float* __restrict__ res,
    float* __restrict__ Cf, bf16* __restrict__ Chi, bf16* __restrict__ Clo,
    int M, int Nn, int K)
{
    extern __shared__ char smem[];
    uint32_t sbase = smem_u32(smem);
    int tid = threadIdx.x;
    int wid = tid >> 5, lane = tid & 31;
    int wm = wid >> 1, wn = wid & 1;          // warp grid 4(m) x 2(n); tile 32x32
    int rowBase = blockIdx.y * 128;
    int colBase = blockIdx.x * 64;

    float acc[2][4][4];                        // [mtile16][ntile8][c0..c3]
#pragma unroll
    for (int a = 0; a < 2; a++)
#pragma unroll
        for (int b = 0; b < 4; b++)
#pragma unroll
            for (int c = 0; c < 4; c++) acc[a][b][c] = 0.f;

    int nChunks = (K + 63) / 64;

    auto issue = [&](int c, int s) {
        uint32_t sb = sbase + s * BUF_BYTES;
        int kb = c * 64;
        load_planeA(Ah, rowBase, M,  K, kb, sb);
        load_planeA(Al, rowBase, M,  K, kb, sb + TILE_A);
        load_planeB(Bh, colBase, Nn, K, kb, sb + 2 * TILE_A);
        load_planeB(Bl, colBase, Nn, K, kb, sb + 2 * TILE_A + TILE_B);
    };

    issue(0, 0);
    CP_COMMIT();
    if (nChunks > 1) issue(1, 1);
    CP_COMMIT();

    // per-lane ldmatrix offsets (within a plane)
    int aRow = wm * 32 + (lane & 15);                      // + mt*16
    int aKb  = (lane >> 4) << 4;                           // 0 or 16 bytes
    int bRowP = wn * 32 + ((lane >> 4) << 3) + (lane & 7); // + p*16
    int bKb  = ((lane >> 3) & 1) << 4;                     // 0 or 16 bytes

    for (int c = 0; c < nChunks; c++) {
        CP_WAIT1();                 // chunk c resident (c+1 still in flight)
        __syncthreads();

        uint32_t pA_h = sbase + (c & 1) * BUF_BYTES;
        uint32_t pA_l = pA_h + TILE_A;
        uint32_t pB_h = pA_h + 2 * TILE_A;
        uint32_t pB_l = pB_h + TILE_B;

        int rem = K - c * 64;
        int ksteps = rem >= 64 ? 4 : (rem + 15) >> 4;
        for (int ks = 0; ks < ksteps; ks++) {
            int kbyte = ks * 32;
            uint32_t ah[2][4], al[2][4], bh[2][4], bl[2][4];
#pragma unroll
            for (int mt = 0; mt < 2; mt++) {
                int off = (aRow + mt * 16) * 128 + kbyte + aKb;
                ldsm4(ah[mt], pA_h + SWZ128(off));
                ldsm4(al[mt], pA_l + SWZ128(off));
            }
#pragma unroll
            for (int p = 0; p < 2; p++) {       // each x4 covers two n8-tiles
                int off = (bRowP + p * 16) * 128 + kbyte + bKb;
                ldsm4(bh[p], pB_h + SWZ128(off));
                ldsm4(bl[p], pB_l + SWZ128(off));
            }
#pragma unroll
            for (int mt = 0; mt < 2; mt++)
#pragma unroll
                for (int p = 0; p < 2; p++) {
                    mma16816(acc[mt][2 * p],     ah[mt], bh[p]);
                    mma16816(acc[mt][2 * p],     ah[mt], bl[p]);
                    mma16816(acc[mt][2 * p],     al[mt], bh[p]);
                    mma16816(acc[mt][2 * p + 1], ah[mt], bh[p] + 2);
                    mma16816(acc[mt][2 * p + 1], ah[mt], bl[p] + 2);
                    mma16816(acc[mt][2 * p + 1], al[mt], bh[p] + 2);
                }
        }
        __syncthreads();            // done reading stage (c&1)
        if (c + 2 < nChunks) {      // refill it; c+1 already in flight
            issue(c + 2, c & 1);
        }
        CP_COMMIT();                // exactly one group per iteration
    }

    // ---------------- epilogue ----------------
#pragma unroll
    for (int mt = 0; mt < 2; mt++) {
        int r0 = rowBase + wm * 32 + mt * 16 + (lane >> 2);
#pragma unroll
        for (int half = 0; half < 2; half++) {
            int row = r0 + half * 8;
            if (row >= M) continue;
            int trow = 0;
            if (EPI == 2) {
                int n = row / (Wcfg * Lw);
                int rem2 = row - n * (Wcfg * Lw);
                int w = rem2 / Lw, l = rem2 - w * Lw;
                trow = (n * Tcfg + w + l) * Dcfg;
            }
#pragma unroll
            for (int nt = 0; nt < 4; nt++) {
                int col = colBase + wn * 32 + nt * 8 + ((lane & 3) << 1);
                if (col >= Nn) continue;
                float v0 = acc[mt][nt][half * 2 + 0] + bias[col];
                float v1 = acc[mt][nt][half * 2 + 1] + bias[col + 1];
                if (EPI == 1) {
                    v0 = 0.5f * v0 * (1.f + erff(v0 * 0.70710678118654752440f));
                    v1 = 0.5f * v1 * (1.f + erff(v1 * 0.70710678118654752440f));
                    bf16 h0, l0, h1b, l1b;
                    split32(v0, h0, l0);
                    split32(v1, h1b, l1b);
                    size_t o = (size_t)row * Nn + col;
                    *(__nv_bfloat162*)(Chi + o) = __nv_bfloat162(h0, h1b);
                    *(__nv_bfloat162*)(Clo + o) = __nv_bfloat162(l0, l1b);
                } else {
                    if (EPI == 2) { v0 += res[trow + col]; v1 += res[trow + col + 1]; }
                    if (EPI == 3) {
                        size_t o = (size_t)row * Nn + col;
                        v0 += res[o]; v1 += res[o + 1];
                    }
                    *(float2*)(Cf + (size_t)row * Nn + col) = make_float2(v0, v1);
                }
            }
        }
    }
}

// ---------------- kernel: [N,C,T,V] -> [N,T,D] + PE, emit fp32 + bf16 hi/lo --------
__global__ void k_build_xs(const float* __restrict__ x, const float* __restrict__ pe) {
    int idx = blockIdx.x * 256 + threadIdx.x;
    if (idx >= NT * Dcfg) return;
    int d   = idx % Dcfg;
    int row = idx / Dcfg;
    int t = row % Tcfg, n = row / Tcfg;
    int v = d / Ccfg,   c = d % Ccfg;
    float val = x[((size_t)(n * Ccfg + c) * Tcfg + t) * Vcfg + v] + pe[t * Dcfg + d];
    g_xs[idx] = val;
    split32(val, g_xs_h[idx], g_xs_l[idx]);
}

// ---------------- weight split ----------------
__global__ void k_split(const float* __restrict__ src, bf16* __restrict__ hi,
                        bf16* __restrict__ lo, int n) {
    int i = blockIdx.x * 256 + threadIdx.x;
    if (i < n) split32(src[i], hi[i], lo[i]);
}

// ---------------- attention: one block per window (L=9, H=2, dh=200) ---------------
__global__ void __launch_bounds__(256) k_attn() {
    __shared__ float sbuf[Lw * 3 * Dcfg];     // 9 x 1200 = 43.2 KB
    __shared__ float ssc[2 * Lw * Lw];
    int b = blockIdx.x;
    int n = b / Wcfg, w = b - n * Wcfg;
    int tid = threadIdx.x;

    for (int idx = tid; idx < Lw * 3 * Dcfg; idx += 256) {
        int t = idx / (3 * Dcfg), col = idx - t * (3 * Dcfg);
        sbuf[idx] = g_qkv[(size_t)(n * Tcfg + w + t) * (3 * Dcfg) + col];
    }
    __syncthreads();

    int wid = tid >> 5, lane = tid & 31;
    for (int p = wid; p < 162; p += 8) {
        int h = p / 81, rem = p - h * 81;
        int i = rem / 9, j = rem - i * 9;
        const float* qp = &sbuf[i * 1200 + h * DH];
        const float* kp = &sbuf[j * 1200 + Dcfg + h * DH];
        float s = 0.f;
        for (int d = lane; d < DH; d += 32) s += qp[d] * kp[d];
#pragma unroll
        for (int o = 16; o; o >>= 1) s += __shfl_xor_sync(0xffffffffu, s, o);
        if (lane == 0) ssc[p] = s * 0.07071067811865475f;   // 1/sqrt(200)
    }
    __syncthreads();

    if (tid < 18) {
        float* r = &ssc[tid * 9];
        float m = r[0];
#pragma unroll
        for (int j = 1; j < 9; j++) m = fmaxf(m, r[j]);
        float s = 0.f;
#pragma unroll
        for (int j = 0; j < 9; j++) { float e = expf(r[j] - m); r[j] = e; s += e; }
        float inv = 1.f / s;
#pragma unroll
        for (int j = 0; j < 9; j++) r[j] *= inv;
    }
    __syncthreads();

    size_t obase = (size_t)b * Lw * Dcfg;
    for (int idx = tid; idx < Lw * Dcfg; idx += 256) {
        int i = idx / Dcfg, c = idx - i * Dcfg;
        int h = c / DH;
        const float* att = &ssc[(h * 9 + i) * 9];
        float s = 0.f;
#pragma unroll
        for (int j = 0; j < 9; j++) s += att[j] * sbuf[j * 1200 + 2 * Dcfg + c];
        split32(s, g_attn_h[obase + idx], g_attn_l[obase + idx]);
    }
}

// ---------------- layernorm over rows of 400, in place; optional bf16 planes -------
__global__ void __launch_bounds__(128) k_ln(float* __restrict__ X,
                                            const float* __restrict__ g,
                                            const float* __restrict__ bb,
                                            bf16* __restrict__ hi,
                                            bf16* __restrict__ lo) {
    int row = blockIdx.x;
    float* xr = X + (size_t)row * Dcfg;
    int tid = threadIdx.x;
    float s = 0.f, s2 = 0.f;
    for (int i = tid; i < Dcfg; i += 128) { float v = xr[i]; s += v; s2 += v * v; }
#pragma unroll
    for (int o = 16; o; o >>= 1) {
        s  += __shfl_xor_sync(0xffffffffu, s, o);
        s2 += __shfl_xor_sync(0xffffffffu, s2, o);
    }
    __shared__ float sh[10];
    int wid = tid >> 5, lane = tid & 31;
    if (lane == 0) { sh[wid] = s; sh[4 + wid] = s2; }
    __syncthreads();
    if (tid == 0) {
        float ts  = sh[0] + sh[1] + sh[2] + sh[3];
        float ts2 = sh[4] + sh[5] + sh[6] + sh[7];
        float mu  = ts * (1.f / Dcfg);
        float var = ts2 * (1.f / Dcfg) - mu * mu;
        sh[8] = mu; sh[9] = rsqrtf(var + 1e-5f);
    }
    __syncthreads();
    float mu = sh[8], rstd = sh[9];
    for (int i = tid; i < Dcfg; i += 128) {
        float v = (xr[i] - mu) * rstd * g[i] + bb[i];
        xr[i] = v;
        if (hi) {
            size_t o = (size_t)row * Dcfg + i;
            split32(v, hi[o], lo[o]);
        }
    }
}

// ---------------- overlap-add as gather + output permute [N,T,D]->[N,C,T,V] --------
__global__ void k_gather(float* __restrict__ out) {
    int idx = blockIdx.x * 256 + threadIdx.x;
    if (idx >= NT * Dcfg) return;
    int d = idx % Dcfg;
    int r = idx / Dcfg;
    int t = r % Tcfg, n = r / Tcfg;
    float acc = 0.f;
    int lmax = t < 8 ? t : 8;
    for (int l = 0; l <= lmax; l++) {
        int w0 = 2 * (t - l);
        if (w0 < Wcfg) {
            acc += g_h2[((size_t)((n * Wcfg + w0) * Lw + l)) * Dcfg + d];
            if (w0 + 1 < Wcfg)
                acc += g_h2[((size_t)((n * Wcfg + w0 + 1) * Lw + l)) * Dcfg + d];
        }
    }
    int v = d / Ccfg, c = d % Ccfg;
    out[((size_t)(n * Ccfg + c) * Tcfg + t) * Vcfg + v] = acc;
}

// ---------------- launch ----------------
extern "C" void kernel_launch(void* const* d_in, const int* in_sizes, int n_in,
                              void* d_out, int out_size) {
    (void)in_sizes; (void)n_in; (void)out_size;
    const float* x     = (const float*)d_in[0];
    const float* pe    = (const float*)d_in[1];
    const float* w_in  = (const float*)d_in[2];
    const float* b_in  = (const float*)d_in[3];
    const float* w_out = (const float*)d_in[4];
    const float* b_out = (const float*)d_in[5];
    const float* w1    = (const float*)d_in[6];
    const float* b1    = (const float*)d_in[7];
    const float* w2    = (const float*)d_in[8];
    const float* b2    = (const float*)d_in[9];
    const float* ln1g  = (const float*)d_in[10];
    const float* ln1b  = (const float*)d_in[11];
    const float* ln2g  = (const float*)d_in[12];
    const float* ln2b  = (const float*)d_in[13];
    float* out = (float*)d_out;

    float *xs, *qkv, *h1, *h2;
    bf16 *xsh, *xsl, *winh, *winl, *wouth, *woutl, *w1h, *w1l, *w2h, *w2l;
    bf16 *atth, *attl, *h1h, *h1l, *ffh, *ffl;
    cudaGetSymbolAddress((void**)&xs,    g_xs);
    cudaGetSymbolAddress((void**)&qkv,   g_qkv);
    cudaGetSymbolAddress((void**)&h1,    g_h1);
    cudaGetSymbolAddress((void**)&h2,    g_h2);
    cudaGetSymbolAddress((void**)&xsh,   g_xs_h);
    cudaGetSymbolAddress((void**)&xsl,   g_xs_l);
    cudaGetSymbolAddress((void**)&winh,  g_win_h);
    cudaGetSymbolAddress((void**)&winl,  g_win_l);
    cudaGetSymbolAddress((void**)&wouth, g_wout_h);
    cudaGetSymbolAddress((void**)&woutl, g_wout_l);
    cudaGetSymbolAddress((void**)&w1h,   g_w1_h);
    cudaGetSymbolAddress((void**)&w1l,   g_w1_l);
    cudaGetSymbolAddress((void**)&w2h,   g_w2_h);
    cudaGetSymbolAddress((void**)&w2l,   g_w2_l);
    cudaGetSymbolAddress((void**)&atth,  g_attn_h);
    cudaGetSymbolAddress((void**)&attl,  g_attn_l);
    cudaGetSymbolAddress((void**)&h1h,   g_h1_h);
    cudaGetSymbolAddress((void**)&h1l,   g_h1_l);
    cudaGetSymbolAddress((void**)&ffh,   g_ff_h);
    cudaGetSymbolAddress((void**)&ffl,   g_ff_l);

    cudaFuncSetAttribute(k_mma<0>, cudaFuncAttributeMaxDynamicSharedMemorySize, SMEM_TOTAL);
    cudaFuncSetAttribute(k_mma<1>, cudaFuncAttributeMaxDynamicSharedMemorySize, SMEM_TOTAL);
    cudaFuncSetAttribute(k_mma<2>, cudaFuncAttributeMaxDynamicSharedMemorySize, SMEM_TOTAL);
    cudaFuncSetAttribute(k_mma<3>, cudaFuncAttributeMaxDynamicSharedMemorySize, SMEM_TOTAL);

    // 1. permute + PE (+ bf16 split)
    k_build_xs<<<(NT * Dcfg + 255) / 256, 256>>>(x, pe);

    // weight splits
    k_split<<<(3 * Dcfg * Dcfg + 255) / 256, 256>>>(w_in,  winh,  winl,  3 * Dcfg * Dcfg);
    k_split<<<(Dcfg * Dcfg + 255) / 256, 256>>>(w_out, wouth, woutl, Dcfg * Dcfg);
    k_split<<<(FFc * Dcfg + 255) / 256, 256>>>(w1, w1h, w1l, FFc * Dcfg);
    k_split<<<(Dcfg * FFc + 255) / 256, 256>>>(w2, w2h, w2l, Dcfg * FFc);

    // 2. per-token QKV: [4800,400] @ [1200,400]^T -> fp32
    {
        dim3 g((3 * Dcfg + 63) / 64, (NT + 127) / 128);
        k_mma<0><<<g, 256, SMEM_TOTAL>>>(xsh, xsl, winh, winl, b_in, nullptr,
                                         qkv, nullptr, nullptr, NT, 3 * Dcfg, Dcfg);
    }

    // 3. windowed attention -> bf16 hi/lo planes
    k_attn<<<NW, 256>>>();

    // 4. out-proj + residual (gathered xs) -> h1 fp32, then LN1 (+ planes)
    {
        dim3 g((Dcfg + 63) / 64, (M2 + 127) / 128);
        k_mma<2><<<g, 256, SMEM_TOTAL>>>(atth, attl, wouth, woutl, b_out, xs,
                                         h1, nullptr, nullptr, M2, Dcfg, Dcfg);
    }
    k_ln<<<M2, 128>>>(h1, ln1g, ln1b, h1h, h1l);

    // 5. FFN up + gelu -> ff bf16 planes (no fp32 intermediate)
    {
        dim3 g((FFc + 63) / 64, (M2 + 127) / 128);
        k_mma<1><<<g, 256, SMEM_TOTAL>>>(h1h, h1l, w1h, w1l, b1, nullptr,
                                         nullptr, ffh, ffl, M2, FFc, Dcfg);
    }
    // 6. FFN down + residual -> h2 fp32, then LN2
    {
        dim3 g((Dcfg + 63) / 64, (M2 + 127) / 128);
        k_mma<3><<<g, 256, SMEM_TOTAL>>>(ffh, ffl, w2h, w2l, b2, h1,
                                         h2, nullptr, nullptr, M2, Dcfg, FFc);
    }
    k_ln<<<M2, 128>>>(h2, ln2g, ln2b, nullptr, nullptr);

    // 7. overlap-add gather + output permute
    k_gather<<<(NT * Dcfg + 255) / 256, 256>>>(out);
}

// round 12
// speedup vs baseline: 3.8208x; 1.9029x over previous
#include <cuda_runtime.h>
#include <cuda_fp16.h>
#include <cstdint>
#include <math.h>

// ---------------- problem constants ----------------
#define Ncfg 16
#define Ccfg 16
#define Tcfg 300
#define Vcfg 25
#define Dcfg 400           // C*V
#define DH   200           // head dim (H=2)
#define FFc  1600
#define Lw   9
#define Wcfg 291           // T - L
#define NW   (Ncfg*Wcfg)   // 4656 windows
#define M2   (NW*Lw)       // 41904 window rows
#define NT   (Ncfg*Tcfg)   // 4800 tokens

typedef __half hf;

// ---------------- scratch (device globals; no allocs allowed) ----------------
__device__ float g_xs   [NT * Dcfg];
__device__ hf    g_xs_f [NT * Dcfg];
__device__ hf    g_win_f[3 * Dcfg * Dcfg];
__device__ hf    g_wout_f[Dcfg * Dcfg];
__device__ hf    g_w1_f [FFc * Dcfg];
__device__ hf    g_w2_f [Dcfg * FFc];
__device__ float g_qkv  [NT * 3 * Dcfg];
__device__ hf    g_attn_f[M2 * Dcfg];
__device__ float g_h1   [M2 * Dcfg];
__device__ hf    g_h1_f [M2 * Dcfg];
__device__ hf    g_ff_f [(size_t)M2 * FFc];
__device__ float g_h2   [M2 * Dcfg];

// ---------------- helpers ----------------
__device__ __forceinline__ uint32_t smem_u32(const void* p) {
    uint32_t a;
    asm("{ .reg .u64 t; cvta.to.shared.u64 t, %1; cvt.u32.u64 %0, t; }" : "=r"(a) : "l"(p));
    return a;
}
#define SWZ128(o) ((o) ^ (((o) >> 3) & 0x70))

__device__ __forceinline__ void ldsm4(uint32_t* r, uint32_t a) {
    asm volatile("ldmatrix.sync.aligned.m8n8.x4.shared.b16 {%0,%1,%2,%3}, [%4];"
        : "=r"(r[0]), "=r"(r[1]), "=r"(r[2]), "=r"(r[3]) : "r"(a));
}
// mma m16n8k16 row.col f32 += f16*f16
__device__ __forceinline__ void mma16816(float* c, const uint32_t* a, const uint32_t* b) {
    asm volatile("mma.sync.aligned.m16n8k16.row.col.f32.f16.f16.f32 "
        "{%0,%1,%2,%3}, {%4,%5,%6,%7}, {%8,%9}, {%0,%1,%2,%3};"
        : "+f"(c[0]), "+f"(c[1]), "+f"(c[2]), "+f"(c[3])
        : "r"(a[0]), "r"(a[1]), "r"(a[2]), "r"(a[3]), "r"(b[0]), "r"(b[1]));
}
#define CP_COMMIT() asm volatile("cp.async.commit_group;" ::: "memory")
#define CP_WAIT1()  asm volatile("cp.async.wait_group 1;" ::: "memory")

// ---------------- smem: [A 16K][B 8K] x 2 stages = 48 KB -> 4 CTAs/SM --------------
// Block tile 128(M) x 64(N) x 64(K), fp16 operands.
#define TILE_A   16384                   // 128 rows x 128B
#define TILE_B   8192                    // 64 rows x 128B
#define BUF_BYTES (TILE_A + TILE_B)      // 24576
#define SMEM_TOTAL (2 * BUF_BYTES)       // 49152

// async-copy a 128x64 fp16 plane (A) into swizzled smem (256 threads)
__device__ __forceinline__ void load_planeA(const hf* __restrict__ G, int rowBase,
                                            int rows, int K, int kbase, uint32_t sdst) {
    int t = threadIdx.x;
    int r = t >> 1, half = t & 1;
    int gr = rowBase + r;
    bool rok = gr < rows;
    const hf* gp = G + (size_t)(rok ? gr : 0) * K;
#pragma unroll
    for (int i = 0; i < 4; i++) {
        int kc = kbase + half * 32 + i * 8;
        int boff = r * 128 + half * 64 + i * 16;
        uint32_t dst = sdst + SWZ128(boff);
        int srcsz = (rok && kc + 8 <= K) ? 16 : 0;
        asm volatile("cp.async.cg.shared.global [%0], [%1], 16, %2;"
                     :: "r"(dst), "l"(gp + kc), "r"(srcsz));
    }
}
// async-copy a 64x64 fp16 plane (B) into swizzled smem (256 threads)
__device__ __forceinline__ void load_planeB(const hf* __restrict__ G, int rowBase,
                                            int rows, int K, int kbase, uint32_t sdst) {
    int t = threadIdx.x;
    int r = t >> 2, q = t & 3;
    int gr = rowBase + r;
    bool rok = gr < rows;
    const hf* gp = G + (size_t)(rok ? gr : 0) * K;
#pragma unroll
    for (int i = 0; i < 2; i++) {
        int g8 = q + i * 4;                     // granule 0..7
        int kc = kbase + g8 * 8;
        int boff = r * 128 + g8 * 16;
        uint32_t dst = sdst + SWZ128(boff);
        int srcsz = (rok && kc + 8 <= K) ? 16 : 0;
        asm volatile("cp.async.cg.shared.global [%0], [%1], 16, %2;"
                     :: "r"(dst), "l"(gp + kc), "r"(srcsz));
    }
}

// ---------------- HMMA GEMM: C[M,Nn] = A[M,K] @ B[Nn,K]^T + bias, epilogues --------
// fp16 operands, fp32 accumulate (single MMA per fragment pair).
// EPI: 0 bias->fp32 | 1 bias+gelu->fp16 plane | 2 bias+res(gathered xs)->fp32
//      3 bias+res(row)->fp32
template <int EPI>
__global__ void __launch_bounds__(256, 3) k_mma(
    const hf* __restrict__ A, const hf* __restrict__ B,
    const float* __restrict__ bias, const float* __restrict__ res,
    float* __restrict__ Cf, hf* __restrict__ Ch,
    int M, int Nn, int K)
{
    extern __shared__ char smem[];
    uint32_t sbase = smem_u32(smem);
    int tid = threadIdx.x;
    int wid = tid >> 5, lane = tid & 31;
    int wm = wid >> 1, wn = wid & 1;          // warp grid 4(m) x 2(n); tile 32x32
    int rowBase = blockIdx.y * 128;
    int colBase = blockIdx.x * 64;

    float acc[2][4][4];                        // [mtile16][ntile8][c0..c3]
#pragma unroll
    for (int a = 0; a < 2; a++)
#pragma unroll
        for (int b = 0; b < 4; b++)
#pragma unroll
            for (int c = 0; c < 4; c++) acc[a][b][c] = 0.f;

    int nChunks = (K + 63) / 64;

    auto issue = [&](int c, int s) {
        uint32_t sb = sbase + s * BUF_BYTES;
        int kb = c * 64;
        load_planeA(A, rowBase, M,  K, kb, sb);
        load_planeB(B, colBase, Nn, K, kb, sb + TILE_A);
    };

    issue(0, 0);
    CP_COMMIT();
    if (nChunks > 1) issue(1, 1);
    CP_COMMIT();

    // per-lane ldmatrix offsets (within a plane)
    int aRow = wm * 32 + (lane & 15);                      // + mt*16
    int aKb  = (lane >> 4) << 4;                           // 0 or 16 bytes
    int bRowP = wn * 32 + ((lane >> 4) << 3) + (lane & 7); // + p*16
    int bKb  = ((lane >> 3) & 1) << 4;                     // 0 or 16 bytes

    for (int c = 0; c < nChunks; c++) {
        CP_WAIT1();                 // chunk c resident (c+1 still in flight)
        __syncthreads();

        uint32_t pA = sbase + (c & 1) * BUF_BYTES;
        uint32_t pB = pA + TILE_A;

        int rem = K - c * 64;
        int ksteps = rem >= 64 ? 4 : (rem + 15) >> 4;
        for (int ks = 0; ks < ksteps; ks++) {
            int kbyte = ks * 32;
            uint32_t af[2][4], bf[2][4];
#pragma unroll
            for (int mt = 0; mt < 2; mt++) {
                int off = (aRow + mt * 16) * 128 + kbyte + aKb;
                ldsm4(af[mt], pA + SWZ128(off));
            }
#pragma unroll
            for (int p = 0; p < 2; p++) {       // each x4 covers two n8-tiles
                int off = (bRowP + p * 16) * 128 + kbyte + bKb;
                ldsm4(bf[p], pB + SWZ128(off));
            }
#pragma unroll
            for (int mt = 0; mt < 2; mt++)
#pragma unroll
                for (int p = 0; p < 2; p++) {
                    mma16816(acc[mt][2 * p],     af[mt], bf[p]);
                    mma16816(acc[mt][2 * p + 1], af[mt], bf[p] + 2);
                }
        }
        __syncthreads();            // done reading stage (c&1)
        if (c + 2 < nChunks) {      // refill it; c+1 already in flight
            issue(c + 2, c & 1);
        }
        CP_COMMIT();                // exactly one group per iteration
    }

    // ---------------- epilogue ----------------
#pragma unroll
    for (int mt = 0; mt < 2; mt++) {
        int r0 = rowBase + wm * 32 + mt * 16 + (lane >> 2);
#pragma unroll
        for (int half = 0; half < 2; half++) {
            int row = r0 + half * 8;
            if (row >= M) continue;
            int trow = 0;
            if (EPI == 2) {
                int n = row / (Wcfg * Lw);
                int rem2 = row - n * (Wcfg * Lw);
                int w = rem2 / Lw, l = rem2 - w * Lw;
                trow = (n * Tcfg + w + l) * Dcfg;
            }
#pragma unroll
            for (int nt = 0; nt < 4; nt++) {
                int col = colBase + wn * 32 + nt * 8 + ((lane & 3) << 1);
                if (col >= Nn) continue;
                float v0 = acc[mt][nt][half * 2 + 0] + bias[col];
                float v1 = acc[mt][nt][half * 2 + 1] + bias[col + 1];
                if (EPI == 1) {
                    v0 = 0.5f * v0 * (1.f + erff(v0 * 0.70710678118654752440f));
                    v1 = 0.5f * v1 * (1.f + erff(v1 * 0.70710678118654752440f));
                    size_t o = (size_t)row * Nn + col;
                    *(__half2*)(Ch + o) = __floats2half2_rn(v0, v1);
                } else {
                    if (EPI == 2) { v0 += res[trow + col]; v1 += res[trow + col + 1]; }
                    if (EPI == 3) {
                        size_t o = (size_t)row * Nn + col;
                        v0 += res[o]; v1 += res[o + 1];
                    }
                    *(float2*)(Cf + (size_t)row * Nn + col) = make_float2(v0, v1);
                }
            }
        }
    }
}

// ---------------- kernel: [N,C,T,V] -> [N,T,D] + PE, emit fp32 + fp16 --------------
__global__ void k_build_xs(const float* __restrict__ x, const float* __restrict__ pe) {
    int idx = blockIdx.x * 256 + threadIdx.x;
    if (idx >= NT * Dcfg) return;
    int d   = idx % Dcfg;
    int row = idx / Dcfg;
    int t = row % Tcfg, n = row / Tcfg;
    int v = d / Ccfg,   c = d % Ccfg;
    float val = x[((size_t)(n * Ccfg + c) * Tcfg + t) * Vcfg + v] + pe[t * Dcfg + d];
    g_xs[idx] = val;
    g_xs_f[idx] = __float2half(val);
}

// ---------------- fp32 -> fp16 conversion ----------------
__global__ void k_tohalf(const float* __restrict__ src, hf* __restrict__ dst, int n) {
    int i = blockIdx.x * 256 + threadIdx.x;
    if (i < n) dst[i] = __float2half(src[i]);
}

// ---------------- attention: one block per window (L=9, H=2, dh=200) ---------------
__global__ void __launch_bounds__(256) k_attn() {
    __shared__ float sbuf[Lw * 3 * Dcfg];     // 9 x 1200 = 43.2 KB
    __shared__ float ssc[2 * Lw * Lw];
    int b = blockIdx.x;
    int n = b / Wcfg, w = b - n * Wcfg;
    int tid = threadIdx.x;

    for (int idx = tid; idx < Lw * 3 * Dcfg; idx += 256) {
        int t = idx / (3 * Dcfg), col = idx - t * (3 * Dcfg);
        sbuf[idx] = g_qkv[(size_t)(n * Tcfg + w + t) * (3 * Dcfg) + col];
    }
    __syncthreads();

    int wid = tid >> 5, lane = tid & 31;
    for (int p = wid; p < 162; p += 8) {
        int h = p / 81, rem = p - h * 81;
        int i = rem / 9, j = rem - i * 9;
        const float* qp = &sbuf[i * 1200 + h * DH];
        const float* kp = &sbuf[j * 1200 + Dcfg + h * DH];
        float s = 0.f;
        for (int d = lane; d < DH; d += 32) s += qp[d] * kp[d];
#pragma unroll
        for (int o = 16; o; o >>= 1) s += __shfl_xor_sync(0xffffffffu, s, o);
        if (lane == 0) ssc[p] = s * 0.07071067811865475f;   // 1/sqrt(200)
    }
    __syncthreads();

    if (tid < 18) {
        float* r = &ssc[tid * 9];
        float m = r[0];
#pragma unroll
        for (int j = 1; j < 9; j++) m = fmaxf(m, r[j]);
        float s = 0.f;
#pragma unroll
        for (int j = 0; j < 9; j++) { float e = expf(r[j] - m); r[j] = e; s += e; }
        float inv = 1.f / s;
#pragma unroll
        for (int j = 0; j < 9; j++) r[j] *= inv;
    }
    __syncthreads();

    size_t obase = (size_t)b * Lw * Dcfg;
    for (int idx = tid; idx < Lw * Dcfg; idx += 256) {
        int i = idx / Dcfg, c = idx - i * Dcfg;
        int h = c / DH;
        const float* att = &ssc[(h * 9 + i) * 9];
        float s = 0.f;
#pragma unroll
        for (int j = 0; j < 9; j++) s += att[j] * sbuf[j * 1200 + 2 * Dcfg + c];
        g_attn_f[obase + idx] = __float2half(s);
    }
}

// ---------------- layernorm over rows of 400, in place; optional fp16 plane --------
__global__ void __launch_bounds__(128) k_ln(float* __restrict__ X,
                                            const float* __restrict__ g,
                                            const float* __restrict__ bb,
                                            hf* __restrict__ out16) {
    int row = blockIdx.x;
    float* xr = X + (size_t)row * Dcfg;
    int tid = threadIdx.x;
    float s = 0.f, s2 = 0.f;
    for (int i = tid; i < Dcfg; i += 128) { float v = xr[i]; s += v; s2 += v * v; }
#pragma unroll
    for (int o = 16; o; o >>= 1) {
        s  += __shfl_xor_sync(0xffffffffu, s, o);
        s2 += __shfl_xor_sync(0xffffffffu, s2, o);
    }
    __shared__ float sh[10];
    int wid = tid >> 5, lane = tid & 31;
    if (lane == 0) { sh[wid] = s; sh[4 + wid] = s2; }
    __syncthreads();
    if (tid == 0) {
        float ts  = sh[0] + sh[1] + sh[2] + sh[3];
        float ts2 = sh[4] + sh[5] + sh[6] + sh[7];
        float mu  = ts * (1.f / Dcfg);
        float var = ts2 * (1.f / Dcfg) - mu * mu;
        sh[8] = mu; sh[9] = rsqrtf(var + 1e-5f);
    }
    __syncthreads();
    float mu = sh[8], rstd = sh[9];
    for (int i = tid; i < Dcfg; i += 128) {
        float v = (xr[i] - mu) * rstd * g[i] + bb[i];
        xr[i] = v;
        if (out16) out16[(size_t)row * Dcfg + i] = __float2half(v);
    }
}

// ---------------- overlap-add as gather + output permute [N,T,D]->[N,C,T,V] --------
__global__ void k_gather(float* __restrict__ out) {
    int idx = blockIdx.x * 256 + threadIdx.x;
    if (idx >= NT * Dcfg) return;
    int d = idx % Dcfg;
    int r = idx / Dcfg;
    int t = r % Tcfg, n = r / Tcfg;
    float acc = 0.f;
    int lmax = t < 8 ? t : 8;
    for (int l = 0; l <= lmax; l++) {
        int w0 = 2 * (t - l);
        if (w0 < Wcfg) {
            acc += g_h2[((size_t)((n * Wcfg + w0) * Lw + l)) * Dcfg + d];
            if (w0 + 1 < Wcfg)
                acc += g_h2[((size_t)((n * Wcfg + w0 + 1) * Lw + l)) * Dcfg + d];
        }
    }
    int v = d / Ccfg, c = d % Ccfg;
    out[((size_t)(n * Ccfg + c) * Tcfg + t) * Vcfg + v] = acc;
}

// ---------------- launch ----------------
extern "C" void kernel_launch(void* const* d_in, const int* in_sizes, int n_in,
                              void* d_out, int out_size) {
    (void)in_sizes; (void)n_in; (void)out_size;
    const float* x     = (const float*)d_in[0];
    const float* pe    = (const float*)d_in[1];
    const float* w_in  = (const float*)d_in[2];
    const float* b_in  = (const float*)d_in[3];
    const float* w_out = (const float*)d_in[4];
    const float* b_out = (const float*)d_in[5];
    const float* w1    = (const float*)d_in[6];
    const float* b1    = (const float*)d_in[7];
    const float* w2    = (const float*)d_in[8];
    const float* b2    = (const float*)d_in[9];
    const float* ln1g  = (const float*)d_in[10];
    const float* ln1b  = (const float*)d_in[11];
    const float* ln2g  = (const float*)d_in[12];
    const float* ln2b  = (const float*)d_in[13];
    float* out = (float*)d_out;

    float *xs, *qkv, *h1, *h2;
    hf *xsf, *winf, *woutf, *w1f, *w2f, *attf, *h1f, *fff;
    cudaGetSymbolAddress((void**)&xs,    g_xs);
    cudaGetSymbolAddress((void**)&qkv,   g_qkv);
    cudaGetSymbolAddress((void**)&h1,    g_h1);
    cudaGetSymbolAddress((void**)&h2,    g_h2);
    cudaGetSymbolAddress((void**)&xsf,   g_xs_f);
    cudaGetSymbolAddress((void**)&winf,  g_win_f);
    cudaGetSymbolAddress((void**)&woutf, g_wout_f);
    cudaGetSymbolAddress((void**)&w1f,   g_w1_f);
    cudaGetSymbolAddress((void**)&w2f,   g_w2_f);
    cudaGetSymbolAddress((void**)&attf,  g_attn_f);
    cudaGetSymbolAddress((void**)&h1f,   g_h1_f);
    cudaGetSymbolAddress((void**)&fff,   g_ff_f);

    cudaFuncSetAttribute(k_mma<0>, cudaFuncAttributeMaxDynamicSharedMemorySize, SMEM_TOTAL);
    cudaFuncSetAttribute(k_mma<1>, cudaFuncAttributeMaxDynamicSharedMemorySize, SMEM_TOTAL);
    cudaFuncSetAttribute(k_mma<2>, cudaFuncAttributeMaxDynamicSharedMemorySize, SMEM_TOTAL);
    cudaFuncSetAttribute(k_mma<3>, cudaFuncAttributeMaxDynamicSharedMemorySize, SMEM_TOTAL);

    // 1. permute + PE (+ fp16)
    k_build_xs<<<(NT * Dcfg + 255) / 256, 256>>>(x, pe);

    // weight conversions
    k_tohalf<<<(3 * Dcfg * Dcfg + 255) / 256, 256>>>(w_in,  winf,  3 * Dcfg * Dcfg);
    k_tohalf<<<(Dcfg * Dcfg + 255) / 256, 256>>>(w_out, woutf, Dcfg * Dcfg);
    k_tohalf<<<(FFc * Dcfg + 255) / 256, 256>>>(w1, w1f, FFc * Dcfg);
    k_tohalf<<<(Dcfg * FFc + 255) / 256, 256>>>(w2, w2f, Dcfg * FFc);

    // 2. per-token QKV: [4800,400] @ [1200,400]^T -> fp32
    {
        dim3 g((3 * Dcfg + 63) / 64, (NT + 127) / 128);
        k_mma<0><<<g, 256, SMEM_TOTAL>>>(xsf, winf, b_in, nullptr,
                                         qkv, nullptr, NT, 3 * Dcfg, Dcfg);
    }

    // 3. windowed attention -> fp16 plane
    k_attn<<<NW, 256>>>();

    // 4. out-proj + residual (gathered xs) -> h1 fp32, then LN1 (+ fp16)
    {
        dim3 g((Dcfg + 63) / 64, (M2 + 127) / 128);
        k_mma<2><<<g, 256, SMEM_TOTAL>>>(attf, woutf, b_out, xs,
                                         h1, nullptr, M2, Dcfg, Dcfg);
    }
    k_ln<<<M2, 128>>>(h1, ln1g, ln1b, h1f);

    // 5. FFN up + gelu -> ff fp16 (no fp32 intermediate)
    {
        dim3 g((FFc + 63) / 64, (M2 + 127) / 128);
        k_mma<1><<<g, 256, SMEM_TOTAL>>>(h1f, w1f, b1, nullptr,
                                         nullptr, fff, M2, FFc, Dcfg);
    }
    // 6. FFN down + residual -> h2 fp32, then LN2
    {
        dim3 g((Dcfg + 63) / 64, (M2 + 127) / 128);
        k_mma<3><<<g, 256, SMEM_TOTAL>>>(fff, w2f, b2, h1,
                                         h2, nullptr, M2, Dcfg, FFc);
    }
    k_ln<<<M2, 128>>>(h2, ln2g, ln2b, nullptr);

    // 7. overlap-add gather + output permute
    k_gather<<<(NT * Dcfg + 255) / 256, 256>>>(out);
}

// round 13
// speedup vs baseline: 4.1792x; 1.0938x over previous
#include <cuda_runtime.h>
#include <cuda_fp16.h>
#include <cstdint>
#include <math.h>

// ---------------- problem constants ----------------
#define Ncfg 16
#define Ccfg 16
#define Tcfg 300
#define Vcfg 25
#define Dcfg 400           // C*V
#define DH   200           // head dim (H=2)
#define FFc  1600
#define Lw   9
#define Wcfg 291           // T - L
#define NW   (Ncfg*Wcfg)   // 4656 windows
#define M2   (NW*Lw)       // 41904 window rows
#define NT   (Ncfg*Tcfg)   // 4800 tokens

typedef __half hf;

// ---------------- scratch (device globals; no allocs allowed) ----------------
__device__ float g_xs   [NT * Dcfg];
__device__ hf    g_xs_f [NT * Dcfg];
__device__ hf    g_win_f[3 * Dcfg * Dcfg];
__device__ hf    g_wout_f[Dcfg * Dcfg];
__device__ hf    g_w1_f [FFc * Dcfg];
__device__ hf    g_w2_f [Dcfg * FFc];
__device__ float g_qkv  [NT * 3 * Dcfg];
__device__ hf    g_attn_f[M2 * Dcfg];
__device__ float g_h1   [M2 * Dcfg];
__device__ hf    g_h1_f [M2 * Dcfg];
__device__ hf    g_ff_f [(size_t)M2 * FFc];
__device__ float g_h2   [M2 * Dcfg];

// ---------------- helpers ----------------
__device__ __forceinline__ uint32_t smem_u32(const void* p) {
    uint32_t a;
    asm("{ .reg .u64 t; cvta.to.shared.u64 t, %1; cvt.u32.u64 %0, t; }" : "=r"(a) : "l"(p));
    return a;
}
#define SWZ128(o) ((o) ^ (((o) >> 3) & 0x70))

__device__ __forceinline__ void ldsm4(uint32_t* r, uint32_t a) {
    asm volatile("ldmatrix.sync.aligned.m8n8.x4.shared.b16 {%0,%1,%2,%3}, [%4];"
        : "=r"(r[0]), "=r"(r[1]), "=r"(r[2]), "=r"(r[3]) : "r"(a));
}
// mma m16n8k16 row.col f32 += f16*f16
__device__ __forceinline__ void mma16816(float* c, const uint32_t* a, const uint32_t* b) {
    asm volatile("mma.sync.aligned.m16n8k16.row.col.f32.f16.f16.f32 "
        "{%0,%1,%2,%3}, {%4,%5,%6,%7}, {%8,%9}, {%0,%1,%2,%3};"
        : "+f"(c[0]), "+f"(c[1]), "+f"(c[2]), "+f"(c[3])
        : "r"(a[0]), "r"(a[1]), "r"(a[2]), "r"(a[3]), "r"(b[0]), "r"(b[1]));
}
#define CP_COMMIT() asm volatile("cp.async.commit_group;" ::: "memory")
#define CP_WAIT1()  asm volatile("cp.async.wait_group 1;" ::: "memory")

__device__ __forceinline__ void store_half4(hf* p, float4 v) {
    __half2* p2 = (__half2*)p;
    p2[0] = __floats2half2_rn(v.x, v.y);
    p2[1] = __floats2half2_rn(v.z, v.w);
}

// ---------------- smem: [A 16K][B 8K] x 2 stages = 48 KB ----------------
// Block tile 128(M) x 64(N) x 64(K), fp16 operands.
#define TILE_A   16384                   // 128 rows x 128B
#define TILE_B   8192                    // 64 rows x 128B
#define BUF_BYTES (TILE_A + TILE_B)      // 24576
#define SMEM_TOTAL (2 * BUF_BYTES)       // 49152

// async-copy a 128x64 fp16 plane (A) into swizzled smem (256 threads)
__device__ __forceinline__ void load_planeA(const hf* __restrict__ G, int rowBase,
                                            int rows, int K, int kbase, uint32_t sdst) {
    int t = threadIdx.x;
    int r = t >> 1, half = t & 1;
    int gr = rowBase + r;
    bool rok = gr < rows;
    const hf* gp = G + (size_t)(rok ? gr : 0) * K;
#pragma unroll
    for (int i = 0; i < 4; i++) {
        int kc = kbase + half * 32 + i * 8;
        int boff = r * 128 + half * 64 + i * 16;
        uint32_t dst = sdst + SWZ128(boff);
        int srcsz = (rok && kc + 8 <= K) ? 16 : 0;
        asm volatile("cp.async.cg.shared.global [%0], [%1], 16, %2;"
                     :: "r"(dst), "l"(gp + kc), "r"(srcsz));
    }
}
// async-copy a 64x64 fp16 plane (B) into swizzled smem (256 threads)
__device__ __forceinline__ void load_planeB(const hf* __restrict__ G, int rowBase,
                                            int rows, int K, int kbase, uint32_t sdst) {
    int t = threadIdx.x;
    int r = t >> 2, q = t & 3;
    int gr = rowBase + r;
    bool rok = gr < rows;
    const hf* gp = G + (size_t)(rok ? gr : 0) * K;
#pragma unroll
    for (int i = 0; i < 2; i++) {
        int g8 = q + i * 4;                     // granule 0..7
        int kc = kbase + g8 * 8;
        int boff = r * 128 + g8 * 16;
        uint32_t dst = sdst + SWZ128(boff);
        int srcsz = (rok && kc + 8 <= K) ? 16 : 0;
        asm volatile("cp.async.cg.shared.global [%0], [%1], 16, %2;"
                     :: "r"(dst), "l"(gp + kc), "r"(srcsz));
    }
}

// ---------------- HMMA GEMM: C[M,Nn] = A[M,K] @ B[Nn,K]^T + bias, epilogues --------
// fp16 operands, fp32 accumulate.
// EPI: 0 bias->fp32 | 1 bias+gelu->fp16 plane | 2 bias+res(gathered xs)->fp32
//      3 bias+res(row)->fp32
template <int EPI>
__global__ void __launch_bounds__(256, 3) k_mma(
    const hf* __restrict__ A, const hf* __restrict__ B,
    const float* __restrict__ bias, const float* __restrict__ res,
    float* __restrict__ Cf, hf* __restrict__ Ch,
    int M, int Nn, int K)
{
    extern __shared__ char smem[];
    uint32_t sbase = smem_u32(smem);
    int tid = threadIdx.x;
    int wid = tid >> 5, lane = tid & 31;
    int wm = wid >> 1, wn = wid & 1;          // warp grid 4(m) x 2(n); tile 32x32
    int rowBase = blockIdx.y * 128;
    int colBase = blockIdx.x * 64;

    float acc[2][4][4];
#pragma unroll
    for (int a = 0; a < 2; a++)
#pragma unroll
        for (int b = 0; b < 4; b++)
#pragma unroll
            for (int c = 0; c < 4; c++) acc[a][b][c] = 0.f;

    int nChunks = (K + 63) / 64;

    auto issue = [&](int c, int s) {
        uint32_t sb = sbase + s * BUF_BYTES;
        int kb = c * 64;
        load_planeA(A, rowBase, M,  K, kb, sb);
        load_planeB(B, colBase, Nn, K, kb, sb + TILE_A);
    };

    issue(0, 0);
    CP_COMMIT();
    if (nChunks > 1) issue(1, 1);
    CP_COMMIT();

    int aRow = wm * 32 + (lane & 15);
    int aKb  = (lane >> 4) << 4;
    int bRowP = wn * 32 + ((lane >> 4) << 3) + (lane & 7);
    int bKb  = ((lane >> 3) & 1) << 4;

    for (int c = 0; c < nChunks; c++) {
        CP_WAIT1();
        __syncthreads();

        uint32_t pA = sbase + (c & 1) * BUF_BYTES;
        uint32_t pB = pA + TILE_A;

        int rem = K - c * 64;
        int ksteps = rem >= 64 ? 4 : (rem + 15) >> 4;
        for (int ks = 0; ks < ksteps; ks++) {
            int kbyte = ks * 32;
            uint32_t af[2][4], bf[2][4];
#pragma unroll
            for (int mt = 0; mt < 2; mt++) {
                int off = (aRow + mt * 16) * 128 + kbyte + aKb;
                ldsm4(af[mt], pA + SWZ128(off));
            }
#pragma unroll
            for (int p = 0; p < 2; p++) {
                int off = (bRowP + p * 16) * 128 + kbyte + bKb;
                ldsm4(bf[p], pB + SWZ128(off));
            }
#pragma unroll
            for (int mt = 0; mt < 2; mt++)
#pragma unroll
                for (int p = 0; p < 2; p++) {
                    mma16816(acc[mt][2 * p],     af[mt], bf[p]);
                    mma16816(acc[mt][2 * p + 1], af[mt], bf[p] + 2);
                }
        }
        __syncthreads();
        if (c + 2 < nChunks) {
            issue(c + 2, c & 1);
        }
        CP_COMMIT();
    }

    // ---------------- epilogue ----------------
#pragma unroll
    for (int mt = 0; mt < 2; mt++) {
        int r0 = rowBase + wm * 32 + mt * 16 + (lane >> 2);
#pragma unroll
        for (int half = 0; half < 2; half++) {
            int row = r0 + half * 8;
            if (row >= M) continue;
            int trow = 0;
            if (EPI == 2) {
                int n = row / (Wcfg * Lw);
                int rem2 = row - n * (Wcfg * Lw);
                int w = rem2 / Lw, l = rem2 - w * Lw;
                trow = (n * Tcfg + w + l) * Dcfg;
            }
#pragma unroll
            for (int nt = 0; nt < 4; nt++) {
                int col = colBase + wn * 32 + nt * 8 + ((lane & 3) << 1);
                if (col >= Nn) continue;
                float v0 = acc[mt][nt][half * 2 + 0] + bias[col];
                float v1 = acc[mt][nt][half * 2 + 1] + bias[col + 1];
                if (EPI == 1) {
                    v0 = 0.5f * v0 * (1.f + erff(v0 * 0.70710678118654752440f));
                    v1 = 0.5f * v1 * (1.f + erff(v1 * 0.70710678118654752440f));
                    size_t o = (size_t)row * Nn + col;
                    *(__half2*)(Ch + o) = __floats2half2_rn(v0, v1);
                } else {
                    if (EPI == 2) { v0 += res[trow + col]; v1 += res[trow + col + 1]; }
                    if (EPI == 3) {
                        size_t o = (size_t)row * Nn + col;
                        v0 += res[o]; v1 += res[o + 1];
                    }
                    *(float2*)(Cf + (size_t)row * Nn + col) = make_float2(v0, v1);
                }
            }
        }
    }
}

// ---------------- kernel: [N,C,T,V] -> [N,T,D] + PE, emit fp32 + fp16 --------------
__global__ void k_build_xs(const float* __restrict__ x, const float* __restrict__ pe) {
    int idx = blockIdx.x * 256 + threadIdx.x;
    if (idx >= NT * Dcfg) return;
    int d   = idx % Dcfg;
    int row = idx / Dcfg;
    int t = row % Tcfg, n = row / Tcfg;
    int v = d / Ccfg,   c = d % Ccfg;
    float val = x[((size_t)(n * Ccfg + c) * Tcfg + t) * Vcfg + v] + pe[t * Dcfg + d];
    g_xs[idx] = val;
    g_xs_f[idx] = __float2half(val);
}

// ---------------- fp32 -> fp16 conversion (vectorized; n % 4 == 0) -----------------
__global__ void k_tohalf(const float* __restrict__ src, hf* __restrict__ dst, int n4) {
    int i = blockIdx.x * 256 + threadIdx.x;
    if (i >= n4) return;
    float4 v = ((const float4*)src)[i];
    store_half4(dst + (size_t)i * 4, v);
}

// ---------------- attention: one block per window (L=9, H=2, dh=200) ---------------
__global__ void __launch_bounds__(256) k_attn() {
    __shared__ __align__(16) float sbuf[Lw * 3 * Dcfg];  // 9 x 1200 = 43.2 KB
    __shared__ float ssc[2 * Lw * Lw];
    int b = blockIdx.x;
    int n = b / Wcfg, w = b - n * Wcfg;
    int tid = threadIdx.x;

    // vectorized load: 2700 float4s
    {
        float4* s4 = (float4*)sbuf;
        const float4* q4 = (const float4*)g_qkv;
        size_t base4 = (size_t)(n * Tcfg + w) * 300;   // 1200/4 per row
        for (int idx = tid; idx < Lw * 300; idx += 256) {
            int t = idx / 300, c4 = idx - t * 300;
            s4[t * 300 + c4] = q4[base4 + (size_t)t * 300 + c4];
        }
    }
    __syncthreads();

    int wid = tid >> 5, lane = tid & 31;
    for (int p = wid; p < 162; p += 8) {
        int h = p / 81, rem = p - h * 81;
        int i = rem / 9, j = rem - i * 9;
        const float4* qp = (const float4*)&sbuf[i * 1200 + h * DH];
        const float4* kp = (const float4*)&sbuf[j * 1200 + Dcfg + h * DH];
        float s = 0.f;
        for (int d4 = lane; d4 < DH / 4; d4 += 32) {
            float4 qv = qp[d4], kv = kp[d4];
            s += qv.x * kv.x + qv.y * kv.y + qv.z * kv.z + qv.w * kv.w;
        }
#pragma unroll
        for (int o = 16; o; o >>= 1) s += __shfl_xor_sync(0xffffffffu, s, o);
        if (lane == 0) ssc[p] = s * 0.07071067811865475f;   // 1/sqrt(200)
    }
    __syncthreads();

    if (tid < 18) {
        float* r = &ssc[tid * 9];
        float m = r[0];
#pragma unroll
        for (int j = 1; j < 9; j++) m = fmaxf(m, r[j]);
        float s = 0.f;
#pragma unroll
        for (int j = 0; j < 9; j++) { float e = expf(r[j] - m); r[j] = e; s += e; }
        float inv = 1.f / s;
#pragma unroll
        for (int j = 0; j < 9; j++) r[j] *= inv;
    }
    __syncthreads();

    // AV: 900 float4s
    size_t obase = (size_t)b * Lw * Dcfg;
    const float4* s4 = (const float4*)sbuf;
    for (int idx = tid; idx < Lw * 100; idx += 256) {
        int i = idx / 100, c4 = idx - i * 100;
        int h = (c4 >= 50);
        const float* att = &ssc[(h * 9 + i) * 9];
        float4 acc = make_float4(0.f, 0.f, 0.f, 0.f);
#pragma unroll
        for (int j = 0; j < 9; j++) {
            float aj = att[j];
            float4 vv = s4[j * 300 + 200 + c4];   // V starts at col 800 floats = 200 f4
            acc.x += aj * vv.x; acc.y += aj * vv.y;
            acc.z += aj * vv.z; acc.w += aj * vv.w;
        }
        store_half4(&g_attn_f[obase + (size_t)i * Dcfg + c4 * 4], acc);
    }
}

// ---------------- layernorm over rows of 400, in place; optional fp16 plane --------
__global__ void __launch_bounds__(128) k_ln(float* __restrict__ X,
                                            const float* __restrict__ g,
                                            const float* __restrict__ bb,
                                            hf* __restrict__ out16) {
    int row = blockIdx.x;
    float4* xr4 = (float4*)(X + (size_t)row * Dcfg);
    int tid = threadIdx.x;
    float4 v4 = make_float4(0.f, 0.f, 0.f, 0.f);
    float s = 0.f, s2 = 0.f;
    if (tid < 100) {
        v4 = xr4[tid];
        s  = v4.x + v4.y + v4.z + v4.w;
        s2 = v4.x * v4.x + v4.y * v4.y + v4.z * v4.z + v4.w * v4.w;
    }
#pragma unroll
    for (int o = 16; o; o >>= 1) {
        s  += __shfl_xor_sync(0xffffffffu, s, o);
        s2 += __shfl_xor_sync(0xffffffffu, s2, o);
    }
    __shared__ float sh[10];
    int wid = tid >> 5, lane = tid & 31;
    if (lane == 0) { sh[wid] = s; sh[4 + wid] = s2; }
    __syncthreads();
    if (tid == 0) {
        float ts  = sh[0] + sh[1] + sh[2] + sh[3];
        float ts2 = sh[4] + sh[5] + sh[6] + sh[7];
        float mu  = ts * (1.f / Dcfg);
        float var = ts2 * (1.f / Dcfg) - mu * mu;
        sh[8] = mu; sh[9] = rsqrtf(var + 1e-5f);
    }
    __syncthreads();
    float mu = sh[8], rstd = sh[9];
    if (tid < 100) {
        float4 g4 = ((const float4*)g)[tid];
        float4 b4 = ((const float4*)bb)[tid];
        float4 r;
        r.x = (v4.x - mu) * rstd * g4.x + b4.x;
        r.y = (v4.y - mu) * rstd * g4.y + b4.y;
        r.z = (v4.z - mu) * rstd * g4.z + b4.z;
        r.w = (v4.w - mu) * rstd * g4.w + b4.w;
        xr4[tid] = r;
        if (out16) store_half4(out16 + (size_t)row * Dcfg + tid * 4, r);
    }
}

// ---------------- overlap-add gather + output permute [N,T,D]->[N,C,T,V], f4 -------
__global__ void k_gather(float* __restrict__ out) {
    int idx = blockIdx.x * 256 + threadIdx.x;
    if (idx >= NT * 100) return;               // float4 granules
    int d4 = idx % 100;
    int r = idx / 100;
    int t = r % Tcfg, n = r / Tcfg;
    float4 acc = make_float4(0.f, 0.f, 0.f, 0.f);
    int lmax = t < 8 ? t : 8;
    for (int l = 0; l <= lmax; l++) {
        int w0 = 2 * (t - l);
        if (w0 < Wcfg) {
            const float4* p0 = (const float4*)&g_h2[((size_t)((n * Wcfg + w0) * Lw + l)) * Dcfg];
            float4 a = p0[d4];
            acc.x += a.x; acc.y += a.y; acc.z += a.z; acc.w += a.w;
            if (w0 + 1 < Wcfg) {
                const float4* p1 = (const float4*)&g_h2[((size_t)((n * Wcfg + w0 + 1) * Lw + l)) * Dcfg];
                float4 bq = p1[d4];
                acc.x += bq.x; acc.y += bq.y; acc.z += bq.z; acc.w += bq.w;
            }
        }
    }
    int d = d4 * 4;
    int v = d / Ccfg, c0 = d % Ccfg;
    float vals[4] = {acc.x, acc.y, acc.z, acc.w};
#pragma unroll
    for (int j = 0; j < 4; j++)
        out[((size_t)(n * Ccfg + c0 + j) * Tcfg + t) * Vcfg + v] = vals[j];
}

// ---------------- launch ----------------
extern "C" void kernel_launch(void* const* d_in, const int* in_sizes, int n_in,
                              void* d_out, int out_size) {
    (void)in_sizes; (void)n_in; (void)out_size;
    const float* x     = (const float*)d_in[0];
    const float* pe    = (const float*)d_in[1];
    const float* w_in  = (const float*)d_in[2];
    const float* b_in  = (const float*)d_in[3];
    const float* w_out = (const float*)d_in[4];
    const float* b_out = (const float*)d_in[5];
    const float* w1    = (const float*)d_in[6];
    const float* b1    = (const float*)d_in[7];
    const float* w2    = (const float*)d_in[8];
    const float* b2    = (const float*)d_in[9];
    const float* ln1g  = (const float*)d_in[10];
    const float* ln1b  = (const float*)d_in[11];
    const float* ln2g  = (const float*)d_in[12];
    const float* ln2b  = (const float*)d_in[13];
    float* out = (float*)d_out;

    float *xs, *qkv, *h1, *h2;
    hf *xsf, *winf, *woutf, *w1f, *w2f, *attf, *h1f, *fff;
    cudaGetSymbolAddress((void**)&xs,    g_xs);
    cudaGetSymbolAddress((void**)&qkv,   g_qkv);
    cudaGetSymbolAddress((void**)&h1,    g_h1);
    cudaGetSymbolAddress((void**)&h2,    g_h2);
    cudaGetSymbolAddress((void**)&xsf,   g_xs_f);
    cudaGetSymbolAddress((void**)&winf,  g_win_f);
    cudaGetSymbolAddress((void**)&woutf, g_wout_f);
    cudaGetSymbolAddress((void**)&w1f,   g_w1_f);
    cudaGetSymbolAddress((void**)&w2f,   g_w2_f);
    cudaGetSymbolAddress((void**)&attf,  g_attn_f);
    cudaGetSymbolAddress((void**)&h1f,   g_h1_f);
    cudaGetSymbolAddress((void**)&fff,   g_ff_f);

    cudaFuncSetAttribute(k_mma<0>, cudaFuncAttributeMaxDynamicSharedMemorySize, SMEM_TOTAL);
    cudaFuncSetAttribute(k_mma<1>, cudaFuncAttributeMaxDynamicSharedMemorySize, SMEM_TOTAL);
    cudaFuncSetAttribute(k_mma<2>, cudaFuncAttributeMaxDynamicSharedMemorySize, SMEM_TOTAL);
    cudaFuncSetAttribute(k_mma<3>, cudaFuncAttributeMaxDynamicSharedMemorySize, SMEM_TOTAL);

    // 1. permute + PE (+ fp16)
    k_build_xs<<<(NT * Dcfg + 255) / 256, 256>>>(x, pe);

    // weight conversions (vectorized)
    k_tohalf<<<(3 * Dcfg * Dcfg / 4 + 255) / 256, 256>>>(w_in,  winf,  3 * Dcfg * Dcfg / 4);
    k_tohalf<<<(Dcfg * Dcfg / 4 + 255) / 256, 256>>>(w_out, woutf, Dcfg * Dcfg / 4);
    k_tohalf<<<(FFc * Dcfg / 4 + 255) / 256, 256>>>(w1, w1f, FFc * Dcfg / 4);
    k_tohalf<<<(Dcfg * FFc / 4 + 255) / 256, 256>>>(w2, w2f, Dcfg * FFc / 4);

    // 2. per-token QKV: [4800,400] @ [1200,400]^T -> fp32
    {
        dim3 g((3 * Dcfg + 63) / 64, (NT + 127) / 128);
        k_mma<0><<<g, 256, SMEM_TOTAL>>>(xsf, winf, b_in, nullptr,
                                         qkv, nullptr, NT, 3 * Dcfg, Dcfg);
    }

    // 3. windowed attention -> fp16 plane
    k_attn<<<NW, 256>>>();

    // 4. out-proj + residual (gathered xs) -> h1 fp32, then LN1 (+ fp16)
    {
        dim3 g((Dcfg + 63) / 64, (M2 + 127) / 128);
        k_mma<2><<<g, 256, SMEM_TOTAL>>>(attf, woutf, b_out, xs,
                                         h1, nullptr, M2, Dcfg, Dcfg);
    }
    k_ln<<<M2, 128>>>(h1, ln1g, ln1b, h1f);

    // 5. FFN up + gelu -> ff fp16
    {
        dim3 g((FFc + 63) / 64, (M2 + 127) / 128);
        k_mma<1><<<g, 256, SMEM_TOTAL>>>(h1f, w1f, b1, nullptr,
                                         nullptr, fff, M2, FFc, Dcfg);
    }
    // 6. FFN down + residual -> h2 fp32, then LN2
    {
        dim3 g((Dcfg + 63) / 64, (M2 + 127) / 128);
        k_mma<3><<<g, 256, SMEM_TOTAL>>>(fff, w2f, b2, h1,
                                         h2, nullptr, M2, Dcfg, FFc);
    }
    k_ln<<<M2, 128>>>(h2, ln2g, ln2b, nullptr);

    // 7. overlap-add gather + output permute
    k_gather<<<(NT * 100 + 255) / 256, 256>>>(out);
}